// round 8
// baseline (speedup 1.0000x reference)
#include <cuda_runtime.h>
#include <cstdint>

#define N_ 8
#define C_ 128
#define H_ 64
#define W_ 64
#define HW 4096

typedef unsigned long long u64;

// scratch (no allocs allowed)
__device__ float g_t7 [N_ * C_ * HW];            // 16 MB
__device__ float g_y  [N_ * C_ * HW];            // 16 MB
__device__ float g_up [N_ * 32 * C_ * C_];       // 16 MB split-K partials
__device__ float g_u  [N_ * C_ * C_];            // 512 KB (transposed: [n][ci][co])
__device__ float g_p7t[C_ * C_];                 // p7 transposed [k][co]

// ---- helpers ---------------------------------------------------------------
__device__ __forceinline__ u64 pack2(float a, float b) {
    u64 r;
    asm("mov.b64 %0, {%1, %2};" : "=l"(r) : "f"(a), "f"(b));
    return r;
}
__device__ __forceinline__ void fma2(u64& d, u64 a, u64 b) {
    asm("fma.rn.f32x2 %0, %1, %2, %0;" : "+l"(d) : "l"(a), "l"(b));
}
__device__ __forceinline__ float lo2(u64 v) { return __uint_as_float((unsigned)v); }
__device__ __forceinline__ float hi2(u64 v) { return __uint_as_float((unsigned)(v >> 32)); }

__device__ __forceinline__ uint32_t s2u(const void* p) {
    return (uint32_t)__cvta_generic_to_shared(p);
}
__device__ __forceinline__ void cpa16(uint32_t dst, const void* src) {
    asm volatile("cp.async.cg.shared.global [%0], [%1], 16;" :: "r"(dst), "l"(src));
}
__device__ __forceinline__ void cpa_commit() {
    asm volatile("cp.async.commit_group;" ::: "memory");
}
__device__ __forceinline__ void cpa_wait0() {
    asm volatile("cp.async.wait_group 0;" ::: "memory");
}

// ---------------------------------------------------------------------------
// K0: transpose p7 -> g_p7t[k][co]
// ---------------------------------------------------------------------------
__global__ void k0_tr(const float* __restrict__ p7)
{
    int idx = blockIdx.x * 256 + threadIdx.x;   // 16384
    int kk = idx >> 7, co = idx & 127;
    g_p7t[idx] = p7[co * 128 + kk];
}

// ---------------------------------------------------------------------------
// K1: t7[n,co,row,:] = sum_c p7[co,c] * relu(x[n,c,row,:])
// 128 threads: ty(16) x 8 co (4 f32x2 pairs), tx(8) x 8 w
// double-buffered weight chunks via cp.async
// ---------------------------------------------------------------------------
__global__ void k1_t7(const float* __restrict__ x)
{
    __shared__ __align__(16) float xs [128 * 64];     // relu(x)[ci][w] 32KB
    __shared__ __align__(16) float as2[2][2048];      // p7t chunks [kk][co] 16KB
    const int row = blockIdx.x, n = blockIdx.y;
    const int t = threadIdx.x;
    const int tx = t & 7, ty = t >> 3;
    const float* xn = x + (size_t)n * C_ * HW + row * 64;

#pragma unroll
    for (int r = 0; r < 4; r++)
        cpa16(s2u(&as2[0][r * 512 + t * 4]), &g_p7t[r * 512 + t * 4]);
    cpa_commit();

#pragma unroll
    for (int r = 0; r < 16; r++) {
        int idx4 = r * 512 + t * 4;
        int ci = idx4 >> 6, w = idx4 & 63;
        float4 v = *reinterpret_cast<const float4*>(&xn[(size_t)ci * HW + w]);
        v.x = fmaxf(v.x, 0.f); v.y = fmaxf(v.y, 0.f);
        v.z = fmaxf(v.z, 0.f); v.w = fmaxf(v.w, 0.f);
        *reinterpret_cast<float4*>(&xs[idx4]) = v;
    }

    u64 acc[4][8];
#pragma unroll
    for (int p = 0; p < 4; p++)
#pragma unroll
        for (int j = 0; j < 8; j++) acc[p][j] = 0ull;

    cpa_wait0();
    __syncthreads();

    for (int kb = 0; kb < 8; kb++) {
        const int cur = kb & 1;
        if (kb < 7) {
#pragma unroll
            for (int r = 0; r < 4; r++)
                cpa16(s2u(&as2[cur ^ 1][r * 512 + t * 4]),
                      &g_p7t[(kb + 1) * 2048 + r * 512 + t * 4]);
            cpa_commit();
        }
#pragma unroll
        for (int kk = 0; kk < 16; kk++) {
            int k = kb * 16 + kk;
            float4 b0 = *reinterpret_cast<const float4*>(&xs[k * 64 + tx * 8]);
            float4 b1 = *reinterpret_cast<const float4*>(&xs[k * 64 + tx * 8 + 4]);
            float4 aq0 = *reinterpret_cast<const float4*>(&as2[cur][kk * 128 + ty * 8]);
            float4 aq1 = *reinterpret_cast<const float4*>(&as2[cur][kk * 128 + ty * 8 + 4]);
            u64 a0 = reinterpret_cast<const u64*>(&aq0)[0];
            u64 a1 = reinterpret_cast<const u64*>(&aq0)[1];
            u64 a2 = reinterpret_cast<const u64*>(&aq1)[0];
            u64 a3 = reinterpret_cast<const u64*>(&aq1)[1];
            u64 bb[8];
            bb[0] = pack2(b0.x, b0.x); bb[1] = pack2(b0.y, b0.y);
            bb[2] = pack2(b0.z, b0.z); bb[3] = pack2(b0.w, b0.w);
            bb[4] = pack2(b1.x, b1.x); bb[5] = pack2(b1.y, b1.y);
            bb[6] = pack2(b1.z, b1.z); bb[7] = pack2(b1.w, b1.w);
#pragma unroll
            for (int j = 0; j < 8; j++) {
                fma2(acc[0][j], a0, bb[j]);
                fma2(acc[1][j], a1, bb[j]);
                fma2(acc[2][j], a2, bb[j]);
                fma2(acc[3][j], a3, bb[j]);
            }
        }
        if (kb < 7) { cpa_wait0(); __syncthreads(); }
    }

    float* t7n = g_t7 + (size_t)n * C_ * HW + row * 64;
#pragma unroll
    for (int p = 0; p < 4; p++) {
        int co0 = ty * 8 + 2 * p;
#pragma unroll
        for (int jq = 0; jq < 2; jq++) {
            float4 vl = make_float4(lo2(acc[p][jq*4+0]), lo2(acc[p][jq*4+1]),
                                    lo2(acc[p][jq*4+2]), lo2(acc[p][jq*4+3]));
            float4 vh = make_float4(hi2(acc[p][jq*4+0]), hi2(acc[p][jq*4+1]),
                                    hi2(acc[p][jq*4+2]), hi2(acc[p][jq*4+3]));
            *reinterpret_cast<float4*>(&t7n[(size_t)co0 * HW + tx * 8 + jq * 4]) = vl;
            *reinterpret_cast<float4*>(&t7n[(size_t)(co0 + 1) * HW + tx * 8 + jq * 4]) = vh;
        }
    }
}

// ---------------------------------------------------------------------------
// K2: grouped 3x7 conv, f32x2 along cin; ci-chunks of 4, double-buffered.
// x stored DUPLICATED in smem: (v,v) pairs -> broadcast operand is one LDS.64.
// 128 threads = 32 w-lanes x 4 cin-octs; thread: 8 cin (4 pairs) x 8 h.
// ---------------------------------------------------------------------------
__global__ void __launch_bounds__(128) k2_conv(const float* __restrict__ x,
                                               const float* __restrict__ p10)
{
    __shared__ __align__(16) float xsd[2][3040];  // dup: [ci4][hh10][ww38] x2
    __shared__ __align__(16) float ws [2][2688];  // [ci4][k21][cin32]
    const int tile = blockIdx.x;        // 0..15
    const int g = blockIdx.y, n = blockIdx.z;
    const int h0 = (tile >> 1) * 8, w0 = (tile & 1) * 32;
    const int t = threadIdx.x;          // 128
    const int wl = t & 31, oct = t >> 5;

    float stage[12];
    auto ldg_x = [&](int cc) {
#pragma unroll
        for (int r = 0; r < 12; r++) {
            int idx = r * 128 + t;
            float v = 0.f;
            if (idx < 1520) {
                int ci = idx / 380;
                int rem = idx - ci * 380;
                int hh = rem / 38, ww = rem - hh * 38;
                int hg = h0 - 1 + hh, wg = w0 - 3 + ww;
                if ((unsigned)hg < 64u && (unsigned)wg < 64u)
                    v = __ldg(&x[(((size_t)n * C_ + g * 32 + cc * 4 + ci) * 64 + hg) * 64 + wg]);
            }
            stage[r] = v;
        }
    };
    auto sts_x = [&](int b) {
#pragma unroll
        for (int r = 0; r < 12; r++) {
            int idx = r * 128 + t;
            if (idx < 1520)
                *reinterpret_cast<float2*>(&xsd[b][idx * 2]) =
                    make_float2(stage[r], stage[r]);
        }
    };
    auto cpa_w = [&](int cc, int b) {
        const float* wsrc = p10 + (size_t)(g * 32 + cc * 4) * 672;
        for (int i4 = t * 4; i4 < 2688; i4 += 512)
            cpa16(s2u(&ws[b][i4]), wsrc + i4);
        cpa_commit();
    };

    u64 acc[4][8];
#pragma unroll
    for (int q = 0; q < 4; q++)
#pragma unroll
        for (int hh = 0; hh < 8; hh++) acc[q][hh] = 0ull;

    ldg_x(0);
    cpa_w(0, 0);
    sts_x(0);
    cpa_wait0();
    __syncthreads();

    for (int cc = 0; cc < 8; cc++) {
        const int cur = cc & 1;
        if (cc < 7) {
            ldg_x(cc + 1);        // LDGs in flight during compute
            cpa_w(cc + 1, cur ^ 1);
        }

#pragma unroll 1
        for (int ci = 0; ci < 4; ci++) {
#pragma unroll
            for (int k = 0; k < 21; k++) {
                const int di = k / 7, dj = k - di * 7;
                const float* wp = &ws[cur][(ci * 21 + k) * 32 + oct * 8];
                float4 wqa = *reinterpret_cast<const float4*>(wp);
                float4 wqb = *reinterpret_cast<const float4*>(wp + 4);
                u64 w0p = reinterpret_cast<const u64*>(&wqa)[0];
                u64 w1p = reinterpret_cast<const u64*>(&wqa)[1];
                u64 w2p = reinterpret_cast<const u64*>(&wqb)[0];
                u64 w3p = reinterpret_cast<const u64*>(&wqb)[1];
                const float* xr = &xsd[cur][(((ci * 10 + di) * 38) + wl + dj) * 2];
#pragma unroll
                for (int hh = 0; hh < 8; hh++) {
                    u64 xx = *reinterpret_cast<const u64*>(xr + hh * 76);
                    fma2(acc[0][hh], w0p, xx);
                    fma2(acc[1][hh], w1p, xx);
                    fma2(acc[2][hh], w2p, xx);
                    fma2(acc[3][hh], w3p, xx);
                }
            }
        }
        if (cc < 7) {
            sts_x(cur ^ 1);
            cpa_wait0();
            __syncthreads();
        }
    }

#pragma unroll
    for (int q = 0; q < 4; q++)
#pragma unroll
        for (int hh = 0; hh < 8; hh++) {
            int cin0 = g * 32 + oct * 8 + 2 * q;
            g_y[(((size_t)n * C_ + cin0) * 64 + h0 + hh) * 64 + w0 + wl] = lo2(acc[q][hh]);
            g_y[(((size_t)n * C_ + cin0 + 1) * 64 + h0 + hh) * 64 + w0 + wl] = hi2(acc[q][hh]);
        }
}

// ---------------------------------------------------------------------------
// K3: split-K partials of u[n,co,ci] = (1/64) sum_p t1[n,co,p]*y[n,ci,p]
// 32 chunks of 128 p; 8 sub-chunks of 16 p, double-buffered with reg staging.
// 512 threads; f32x2 along co. A fragments via LDS.128 (row pad 136).
// ---------------------------------------------------------------------------
__global__ void __launch_bounds__(512, 2) k3_part(const float* __restrict__ x,
                                                  const float* __restrict__ p1)
{
    __shared__ __align__(16) float as2[2][16 * 136];  // t1 [kk][co]
    __shared__ __align__(16) float bs [2][16 * 136];  // y  [kk][ci]
    const int kc = blockIdx.x, n = blockIdx.y;
    const int t = threadIdx.x;       // 512
    const int ty = t >> 5, tx = t & 31;
    const int lc = t >> 2, lk0 = (t & 3) * 4;

    const int p0 = kc * 128;
    const float* xp = x   + (size_t)n * C_ * HW + (size_t)lc * HW + p0 + lk0;
    const float* yp = g_y + (size_t)n * C_ * HW + (size_t)lc * HW + p0 + lk0;

    float4 xa, ya; float s;
    auto ldg = [&](int kb) {
        xa = *reinterpret_cast<const float4*>(xp + kb * 16);
        ya = *reinterpret_cast<const float4*>(yp + kb * 16);
        int h = (p0 + kb * 16) >> 6;
        s = p1[lc * 64 + h] * (1.f / 64.f);
    };
    auto sts = [&](int b) {
        as2[b][(lk0 + 0) * 136 + lc] = s * xa.x;
        as2[b][(lk0 + 1) * 136 + lc] = s * xa.y;
        as2[b][(lk0 + 2) * 136 + lc] = s * xa.z;
        as2[b][(lk0 + 3) * 136 + lc] = s * xa.w;
        bs [b][(lk0 + 0) * 136 + lc] = ya.x;
        bs [b][(lk0 + 1) * 136 + lc] = ya.y;
        bs [b][(lk0 + 2) * 136 + lc] = ya.z;
        bs [b][(lk0 + 3) * 136 + lc] = ya.w;
    };

    u64 acc[4][4];
#pragma unroll
    for (int p = 0; p < 4; p++)
#pragma unroll
        for (int j = 0; j < 4; j++) acc[p][j] = 0ull;

    ldg(0); sts(0);
    __syncthreads();

    for (int kb = 0; kb < 8; kb++) {
        const int cur = kb & 1;
        if (kb < 7) ldg(kb + 1);
#pragma unroll
        for (int kk = 0; kk < 16; kk++) {
            float4 b = *reinterpret_cast<const float4*>(&bs[cur][kk * 136 + tx * 4]);
            float4 aq0 = *reinterpret_cast<const float4*>(&as2[cur][kk * 136 + ty * 8]);
            float4 aq1 = *reinterpret_cast<const float4*>(&as2[cur][kk * 136 + ty * 8 + 4]);
            u64 a0 = reinterpret_cast<const u64*>(&aq0)[0];
            u64 a1 = reinterpret_cast<const u64*>(&aq0)[1];
            u64 a2 = reinterpret_cast<const u64*>(&aq1)[0];
            u64 a3 = reinterpret_cast<const u64*>(&aq1)[1];
            u64 bb0 = pack2(b.x, b.x), bb1 = pack2(b.y, b.y);
            u64 bb2 = pack2(b.z, b.z), bb3 = pack2(b.w, b.w);
            fma2(acc[0][0], a0, bb0); fma2(acc[0][1], a0, bb1);
            fma2(acc[0][2], a0, bb2); fma2(acc[0][3], a0, bb3);
            fma2(acc[1][0], a1, bb0); fma2(acc[1][1], a1, bb1);
            fma2(acc[1][2], a1, bb2); fma2(acc[1][3], a1, bb3);
            fma2(acc[2][0], a2, bb0); fma2(acc[2][1], a2, bb1);
            fma2(acc[2][2], a2, bb2); fma2(acc[2][3], a2, bb3);
            fma2(acc[3][0], a3, bb0); fma2(acc[3][1], a3, bb1);
            fma2(acc[3][2], a3, bb2); fma2(acc[3][3], a3, bb3);
        }
        if (kb < 7) { sts(cur ^ 1); __syncthreads(); }
    }

    float* up = g_up + ((size_t)(n * 32 + kc)) * C_ * C_;
#pragma unroll
    for (int p = 0; p < 4; p++) {
        int co0 = ty * 8 + 2 * p;
        float4 vl = make_float4(lo2(acc[p][0]), lo2(acc[p][1]),
                                lo2(acc[p][2]), lo2(acc[p][3]));
        float4 vh = make_float4(hi2(acc[p][0]), hi2(acc[p][1]),
                                hi2(acc[p][2]), hi2(acc[p][3]));
        *reinterpret_cast<float4*>(&up[co0 * 128 + tx * 4]) = vl;
        *reinterpret_cast<float4*>(&up[(co0 + 1) * 128 + tx * 4]) = vh;
    }
}

// K3b: reduce 32 split-K partials; write u transposed: g_u[n][ci][co]
__global__ void k3_red()
{
    int o = blockIdx.x * 256 + threadIdx.x;   // 131072
    int n = o >> 14, r = o & 16383;
    float s = 0.f;
#pragma unroll
    for (int kc = 0; kc < 32; kc++)
        s += g_up[(((size_t)(n * 32 + kc)) << 14) + r];
    int co = r >> 7, ci = r & 127;
    g_u[((size_t)n << 14) + ci * 128 + co] = s;
}

// ---------------------------------------------------------------------------
// K4: out = max( s3 * sum_ci u[n,co,ci]*t2[ci,p],  x[co,p] - 0.2*sum_jj t7 taps )
// double-buffered u chunks via cp.async; epilogue from smem t7 slab.
// ---------------------------------------------------------------------------
__global__ void k4_out(const float* __restrict__ x, const float* __restrict__ p1,
                       float* __restrict__ out)
{
    __shared__ __align__(16) float xs [128 * 64];     // t2[ci][w], later t7[co][w]
    __shared__ __align__(16) float as2[2][2048];      // u chunks [kk=ci][co]
    const int row = blockIdx.x, n = blockIdx.y;
    const int t = threadIdx.x;  // 128
    const int tx = t & 7, ty = t >> 3;
    const float* xn = x + (size_t)n * C_ * HW + row * 64;
    const float* un = g_u + ((size_t)n << 14);

#pragma unroll
    for (int r = 0; r < 4; r++)
        cpa16(s2u(&as2[0][r * 512 + t * 4]), &un[r * 512 + t * 4]);
    cpa_commit();

#pragma unroll
    for (int r = 0; r < 16; r++) {
        int idx4 = r * 512 + t * 4;
        int ci = idx4 >> 6, w = idx4 & 63;
        float s = 1.f + p1[ci * 64 + row];
        float4 v = *reinterpret_cast<const float4*>(&xn[(size_t)ci * HW + w]);
        v.x *= s; v.y *= s; v.z *= s; v.w *= s;
        *reinterpret_cast<float4*>(&xs[idx4]) = v;
    }

    u64 acc[4][8];
#pragma unroll
    for (int p = 0; p < 4; p++)
#pragma unroll
        for (int j = 0; j < 8; j++) acc[p][j] = 0ull;

    cpa_wait0();
    __syncthreads();

    for (int kb = 0; kb < 8; kb++) {
        const int cur = kb & 1;
        if (kb < 7) {
#pragma unroll
            for (int r = 0; r < 4; r++)
                cpa16(s2u(&as2[cur ^ 1][r * 512 + t * 4]),
                      &un[(kb + 1) * 2048 + r * 512 + t * 4]);
            cpa_commit();
        }
#pragma unroll
        for (int kk = 0; kk < 16; kk++) {
            int k = kb * 16 + kk;
            float4 b0 = *reinterpret_cast<const float4*>(&xs[k * 64 + tx * 8]);
            float4 b1 = *reinterpret_cast<const float4*>(&xs[k * 64 + tx * 8 + 4]);
            float4 aq0 = *reinterpret_cast<const float4*>(&as2[cur][kk * 128 + ty * 8]);
            float4 aq1 = *reinterpret_cast<const float4*>(&as2[cur][kk * 128 + ty * 8 + 4]);
            u64 a0 = reinterpret_cast<const u64*>(&aq0)[0];
            u64 a1 = reinterpret_cast<const u64*>(&aq0)[1];
            u64 a2 = reinterpret_cast<const u64*>(&aq1)[0];
            u64 a3 = reinterpret_cast<const u64*>(&aq1)[1];
            u64 bb[8];
            bb[0] = pack2(b0.x, b0.x); bb[1] = pack2(b0.y, b0.y);
            bb[2] = pack2(b0.z, b0.z); bb[3] = pack2(b0.w, b0.w);
            bb[4] = pack2(b1.x, b1.x); bb[5] = pack2(b1.y, b1.y);
            bb[6] = pack2(b1.z, b1.z); bb[7] = pack2(b1.w, b1.w);
#pragma unroll
            for (int j = 0; j < 8; j++) {
                fma2(acc[0][j], a0, bb[j]);
                fma2(acc[1][j], a1, bb[j]);
                fma2(acc[2][j], a2, bb[j]);
                fma2(acc[3][j], a3, bb[j]);
            }
        }
        if (kb < 7) { cpa_wait0(); __syncthreads(); }
    }

    // epilogue: reuse xs for t7[n,:,row,:]
    __syncthreads();
#pragma unroll
    for (int r = 0; r < 16; r++) {
        int idx4 = r * 512 + t * 4;
        int ci = idx4 >> 6, w = idx4 & 63;
        *reinterpret_cast<float4*>(&xs[idx4]) =
            *reinterpret_cast<const float4*>(
                &g_t7[((size_t)n * C_ + ci) * HW + row * 64 + w]);
    }
    __syncthreads();

    const float s3 = 0.01928793f;    // 1/sqrt(2688)
#pragma unroll
    for (int p = 0; p < 4; p++) {
#pragma unroll
        for (int half = 0; half < 2; half++) {
            int co = ty * 8 + 2 * p + half;
            const float* xr = xn + (size_t)co * HW;
            float4 xv0 = *reinterpret_cast<const float4*>(&xr[tx * 8]);
            float4 xv1 = *reinterpret_cast<const float4*>(&xr[tx * 8 + 4]);
            float xv[8] = {xv0.x, xv0.y, xv0.z, xv0.w, xv1.x, xv1.y, xv1.z, xv1.w};
            float res[8];
#pragma unroll
            for (int j = 0; j < 8; j++) {
                int pp = tx * 8 + j;
                float a = half ? hi2(acc[p][j]) : lo2(acc[p][j]);
                float sum = 0.f;
#pragma unroll
                for (int jj = 0; jj < 5; jj++) {
                    int wp = pp + 3 * jj - 6;
                    if ((unsigned)wp < 64u) sum += xs[co * 64 + wp];
                }
                float t12 = xv[j] - 0.2f * sum;
                res[j] = fmaxf(s3 * a, t12);
            }
            float* orow = out + ((size_t)n * C_ + co) * HW + row * 64;
            *reinterpret_cast<float4*>(&orow[tx * 8]) =
                make_float4(res[0], res[1], res[2], res[3]);
            *reinterpret_cast<float4*>(&orow[tx * 8 + 4]) =
                make_float4(res[4], res[5], res[6], res[7]);
        }
    }
}

// ---------------------------------------------------------------------------
extern "C" void kernel_launch(void* const* d_in, const int* in_sizes, int n_in,
                              void* d_out, int out_size)
{
    const float* x   = (const float*)d_in[0];   // (8,128,64,64)
    const float* p1w = (const float*)d_in[1];   // (1,128,64,1)
    const float* p7w = (const float*)d_in[2];   // (128,128)
    const float* p10 = (const float*)d_in[3];   // (2688,32)
    float* out = (float*)d_out;

    k0_tr  <<<64, 256>>>(p7w);
    k1_t7  <<<dim3(64, 8), 128>>>(x);
    k2_conv<<<dim3(16, 4, 8), 128>>>(x, p10);
    k3_part<<<dim3(32, 8), 512>>>(x, p1w);
    k3_red <<<512, 256>>>();
    k4_out <<<dim3(64, 8), 128>>>(x, p1w, out);
}

// round 9
// speedup vs baseline: 1.0004x; 1.0004x over previous
#include <cuda_runtime.h>
#include <cstdint>

#define N_ 8
#define C_ 128
#define H_ 64
#define W_ 64
#define HW 4096

typedef unsigned long long u64;

// scratch (no allocs allowed)
__device__ float g_t7 [N_ * C_ * HW];            // 16 MB
__device__ float g_y  [N_ * C_ * HW];            // 16 MB
__device__ float g_up [N_ * 32 * C_ * C_];       // 16 MB split-K partials
__device__ float g_u  [N_ * C_ * C_];            // 512 KB (transposed: [n][ci][co])
__device__ float g_p7t[C_ * C_];                 // p7 transposed [k][co]

// ---- helpers ---------------------------------------------------------------
__device__ __forceinline__ u64 pack2(float a, float b) {
    u64 r;
    asm("mov.b64 %0, {%1, %2};" : "=l"(r) : "f"(a), "f"(b));
    return r;
}
__device__ __forceinline__ void fma2(u64& d, u64 a, u64 b) {
    asm("fma.rn.f32x2 %0, %1, %2, %0;" : "+l"(d) : "l"(a), "l"(b));
}
__device__ __forceinline__ float lo2(u64 v) { return __uint_as_float((unsigned)v); }
__device__ __forceinline__ float hi2(u64 v) { return __uint_as_float((unsigned)(v >> 32)); }

__device__ __forceinline__ uint32_t s2u(const void* p) {
    return (uint32_t)__cvta_generic_to_shared(p);
}
__device__ __forceinline__ void cpa16(uint32_t dst, const void* src) {
    asm volatile("cp.async.cg.shared.global [%0], [%1], 16;" :: "r"(dst), "l"(src));
}
__device__ __forceinline__ void cpa4z(uint32_t dst, const void* src, bool p) {
    int sz = p ? 4 : 0;
    asm volatile("cp.async.ca.shared.global [%0], [%1], 4, %2;"
                 :: "r"(dst), "l"(src), "r"(sz));
}
__device__ __forceinline__ void cpa_commit() {
    asm volatile("cp.async.commit_group;" ::: "memory");
}
__device__ __forceinline__ void cpa_wait0() {
    asm volatile("cp.async.wait_group 0;" ::: "memory");
}

// ---------------------------------------------------------------------------
// K0: transpose p7 -> g_p7t[k][co]
// ---------------------------------------------------------------------------
__global__ void k0_tr(const float* __restrict__ p7)
{
    int idx = blockIdx.x * 256 + threadIdx.x;   // 16384
    int kk = idx >> 7, co = idx & 127;
    g_p7t[idx] = p7[co * 128 + kk];
}

// ---------------------------------------------------------------------------
// K1: t7[n,co,row,:] = sum_c p7[co,c] * relu(x[n,c,row,:])
// 128 threads: ty(16) x 8 co (4 f32x2 pairs), tx(8) x 8 w
// double-buffered weight chunks via cp.async
// ---------------------------------------------------------------------------
__global__ void k1_t7(const float* __restrict__ x)
{
    __shared__ __align__(16) float xs [128 * 64];     // relu(x)[ci][w] 32KB
    __shared__ __align__(16) float as2[2][2048];      // p7t chunks [kk][co] 16KB
    const int row = blockIdx.x, n = blockIdx.y;
    const int t = threadIdx.x;
    const int tx = t & 7, ty = t >> 3;
    const float* xn = x + (size_t)n * C_ * HW + row * 64;

    // kick off weight chunk 0
#pragma unroll
    for (int r = 0; r < 4; r++)
        cpa16(s2u(&as2[0][r * 512 + t * 4]), &g_p7t[r * 512 + t * 4]);
    cpa_commit();

#pragma unroll
    for (int r = 0; r < 16; r++) {
        int idx4 = r * 512 + t * 4;
        int ci = idx4 >> 6, w = idx4 & 63;
        float4 v = *reinterpret_cast<const float4*>(&xn[(size_t)ci * HW + w]);
        v.x = fmaxf(v.x, 0.f); v.y = fmaxf(v.y, 0.f);
        v.z = fmaxf(v.z, 0.f); v.w = fmaxf(v.w, 0.f);
        *reinterpret_cast<float4*>(&xs[idx4]) = v;
    }

    u64 acc[4][8];
#pragma unroll
    for (int p = 0; p < 4; p++)
#pragma unroll
        for (int j = 0; j < 8; j++) acc[p][j] = 0ull;

    cpa_wait0();
    __syncthreads();

    for (int kb = 0; kb < 8; kb++) {
        const int cur = kb & 1;
        if (kb < 7) {
#pragma unroll
            for (int r = 0; r < 4; r++)
                cpa16(s2u(&as2[cur ^ 1][r * 512 + t * 4]),
                      &g_p7t[(kb + 1) * 2048 + r * 512 + t * 4]);
            cpa_commit();
        }
#pragma unroll
        for (int kk = 0; kk < 16; kk++) {
            int k = kb * 16 + kk;
            float4 b0 = *reinterpret_cast<const float4*>(&xs[k * 64 + tx * 8]);
            float4 b1 = *reinterpret_cast<const float4*>(&xs[k * 64 + tx * 8 + 4]);
            u64 a0 = *reinterpret_cast<const u64*>(&as2[cur][kk * 128 + ty * 8 + 0]);
            u64 a1 = *reinterpret_cast<const u64*>(&as2[cur][kk * 128 + ty * 8 + 2]);
            u64 a2 = *reinterpret_cast<const u64*>(&as2[cur][kk * 128 + ty * 8 + 4]);
            u64 a3 = *reinterpret_cast<const u64*>(&as2[cur][kk * 128 + ty * 8 + 6]);
            u64 bb[8];
            bb[0] = pack2(b0.x, b0.x); bb[1] = pack2(b0.y, b0.y);
            bb[2] = pack2(b0.z, b0.z); bb[3] = pack2(b0.w, b0.w);
            bb[4] = pack2(b1.x, b1.x); bb[5] = pack2(b1.y, b1.y);
            bb[6] = pack2(b1.z, b1.z); bb[7] = pack2(b1.w, b1.w);
#pragma unroll
            for (int j = 0; j < 8; j++) {
                fma2(acc[0][j], a0, bb[j]);
                fma2(acc[1][j], a1, bb[j]);
                fma2(acc[2][j], a2, bb[j]);
                fma2(acc[3][j], a3, bb[j]);
            }
        }
        if (kb < 7) { cpa_wait0(); __syncthreads(); }
    }

    float* t7n = g_t7 + (size_t)n * C_ * HW + row * 64;
#pragma unroll
    for (int p = 0; p < 4; p++) {
        int co0 = ty * 8 + 2 * p;
#pragma unroll
        for (int jq = 0; jq < 2; jq++) {
            float4 vl = make_float4(lo2(acc[p][jq*4+0]), lo2(acc[p][jq*4+1]),
                                    lo2(acc[p][jq*4+2]), lo2(acc[p][jq*4+3]));
            float4 vh = make_float4(hi2(acc[p][jq*4+0]), hi2(acc[p][jq*4+1]),
                                    hi2(acc[p][jq*4+2]), hi2(acc[p][jq*4+3]));
            *reinterpret_cast<float4*>(&t7n[(size_t)co0 * HW + tx * 8 + jq * 4]) = vl;
            *reinterpret_cast<float4*>(&t7n[(size_t)(co0 + 1) * HW + tx * 8 + jq * 4]) = vh;
        }
    }
}

// ---------------------------------------------------------------------------
// K2: grouped 3x7 conv, f32x2 along cin; ci-chunks of 4, double-buffered via
// cp.async (x halo gets zero-fill). dj-major inner loop with register-cached
// x halo column (xv[10]) reused across the 3 vertical taps.
// 128 threads = 32 w-lanes x 4 cin-octs; thread: 8 cin (4 pairs) x 8 h.
// ---------------------------------------------------------------------------
__global__ void __launch_bounds__(128) k2_conv(const float* __restrict__ x,
                                               const float* __restrict__ p10)
{
    __shared__ __align__(16) float xs[2][1520];   // [ci4][hh10][ww38]
    __shared__ __align__(16) float ws[2][2688];   // [ci4][k21][cin32]
    const int tile = blockIdx.x;        // 0..15
    const int g = blockIdx.y, n = blockIdx.z;
    const int h0 = (tile >> 1) * 8, w0 = (tile & 1) * 32;
    const int t = threadIdx.x;          // 128
    const int wl = t & 31, oct = t >> 5;

    auto load_chunk = [&](int cc, int b) {
        for (int idx = t; idx < 1520; idx += 128) {
            int ci = idx / 380;
            int rem = idx - ci * 380;
            int hh = rem / 38, ww = rem - hh * 38;
            int hg = h0 - 1 + hh, wg = w0 - 3 + ww;
            bool p = ((unsigned)hg < 64u) && ((unsigned)wg < 64u);
            const float* src = p
                ? &x[(((size_t)n * C_ + g * 32 + cc * 4 + ci) * 64 + hg) * 64 + wg]
                : x;
            cpa4z(s2u(&xs[b][idx]), src, p);
        }
        const float* wsrc = p10 + (size_t)(g * 32 + cc * 4) * 672;
        for (int i4 = t * 4; i4 < 2688; i4 += 512)
            cpa16(s2u(&ws[b][i4]), wsrc + i4);
        cpa_commit();
    };

    u64 acc[4][8];
#pragma unroll
    for (int q = 0; q < 4; q++)
#pragma unroll
        for (int hh = 0; hh < 8; hh++) acc[q][hh] = 0ull;

    load_chunk(0, 0);
    cpa_wait0();
    __syncthreads();

    for (int cc = 0; cc < 8; cc++) {
        const int cur = cc & 1;
        if (cc < 7) load_chunk(cc + 1, cur ^ 1);

#pragma unroll 1
        for (int ci = 0; ci < 4; ci++) {
#pragma unroll
            for (int dj = 0; dj < 7; dj++) {
                // register-cache the x halo column for this (ci, dj)
                u64 xv[10];
                const float* xcol = &xs[cur][ci * 380 + wl + dj];
#pragma unroll
                for (int r = 0; r < 10; r++) {
                    float v = xcol[r * 38];
                    xv[r] = pack2(v, v);
                }
#pragma unroll
                for (int di = 0; di < 3; di++) {
                    const int k = di * 7 + dj;
                    const float* wp = &ws[cur][(ci * 21 + k) * 32 + oct * 8];
                    float4 wqa = *reinterpret_cast<const float4*>(wp);
                    float4 wqb = *reinterpret_cast<const float4*>(wp + 4);
                    u64 w0p = reinterpret_cast<const u64*>(&wqa)[0];
                    u64 w1p = reinterpret_cast<const u64*>(&wqa)[1];
                    u64 w2p = reinterpret_cast<const u64*>(&wqb)[0];
                    u64 w3p = reinterpret_cast<const u64*>(&wqb)[1];
#pragma unroll
                    for (int hh = 0; hh < 8; hh++) {
                        u64 xx = xv[hh + di];
                        fma2(acc[0][hh], w0p, xx);
                        fma2(acc[1][hh], w1p, xx);
                        fma2(acc[2][hh], w2p, xx);
                        fma2(acc[3][hh], w3p, xx);
                    }
                }
            }
        }
        if (cc < 7) { cpa_wait0(); __syncthreads(); }
    }

#pragma unroll
    for (int q = 0; q < 4; q++)
#pragma unroll
        for (int hh = 0; hh < 8; hh++) {
            int cin0 = g * 32 + oct * 8 + 2 * q;
            g_y[(((size_t)n * C_ + cin0) * 64 + h0 + hh) * 64 + w0 + wl] = lo2(acc[q][hh]);
            g_y[(((size_t)n * C_ + cin0 + 1) * 64 + h0 + hh) * 64 + w0 + wl] = hi2(acc[q][hh]);
        }
}

// ---------------------------------------------------------------------------
// K3: split-K partials of u[n,co,ci] = (1/64) sum_p t1[n,co,p]*y[n,ci,p]
// 32 chunks of 128 p; 8 sub-chunks of 16 p, double-buffered with reg staging.
// 512 threads; f32x2 along co.
// ---------------------------------------------------------------------------
__global__ void __launch_bounds__(512, 2) k3_part(const float* __restrict__ x,
                                                  const float* __restrict__ p1)
{
    __shared__ __align__(16) float as2[2][16 * 132];  // t1 [kk][co]
    __shared__ __align__(16) float bs [2][16 * 132];  // y  [kk][ci]
    const int kc = blockIdx.x, n = blockIdx.y;
    const int t = threadIdx.x;       // 512
    const int ty = t >> 5, tx = t & 31;
    const int lc = t >> 2, lk0 = (t & 3) * 4;

    const int p0 = kc * 128;
    const float* xp = x   + (size_t)n * C_ * HW + (size_t)lc * HW + p0 + lk0;
    const float* yp = g_y + (size_t)n * C_ * HW + (size_t)lc * HW + p0 + lk0;

    float4 xa, ya; float s;
    auto ldg = [&](int kb) {
        xa = *reinterpret_cast<const float4*>(xp + kb * 16);
        ya = *reinterpret_cast<const float4*>(yp + kb * 16);
        int h = (p0 + kb * 16) >> 6;
        s = p1[lc * 64 + h] * (1.f / 64.f);
    };
    auto sts = [&](int b) {
        as2[b][(lk0 + 0) * 132 + lc] = s * xa.x;
        as2[b][(lk0 + 1) * 132 + lc] = s * xa.y;
        as2[b][(lk0 + 2) * 132 + lc] = s * xa.z;
        as2[b][(lk0 + 3) * 132 + lc] = s * xa.w;
        bs [b][(lk0 + 0) * 132 + lc] = ya.x;
        bs [b][(lk0 + 1) * 132 + lc] = ya.y;
        bs [b][(lk0 + 2) * 132 + lc] = ya.z;
        bs [b][(lk0 + 3) * 132 + lc] = ya.w;
    };

    u64 acc[4][4];
#pragma unroll
    for (int p = 0; p < 4; p++)
#pragma unroll
        for (int j = 0; j < 4; j++) acc[p][j] = 0ull;

    ldg(0); sts(0);
    __syncthreads();

    for (int kb = 0; kb < 8; kb++) {
        const int cur = kb & 1;
        if (kb < 7) ldg(kb + 1);
#pragma unroll
        for (int kk = 0; kk < 16; kk++) {
            float4 b = *reinterpret_cast<const float4*>(&bs[cur][kk * 132 + tx * 4]);
            u64 a0 = *reinterpret_cast<const u64*>(&as2[cur][kk * 132 + ty * 8 + 0]);
            u64 a1 = *reinterpret_cast<const u64*>(&as2[cur][kk * 132 + ty * 8 + 2]);
            u64 a2 = *reinterpret_cast<const u64*>(&as2[cur][kk * 132 + ty * 8 + 4]);
            u64 a3 = *reinterpret_cast<const u64*>(&as2[cur][kk * 132 + ty * 8 + 6]);
            u64 bb0 = pack2(b.x, b.x), bb1 = pack2(b.y, b.y);
            u64 bb2 = pack2(b.z, b.z), bb3 = pack2(b.w, b.w);
            fma2(acc[0][0], a0, bb0); fma2(acc[0][1], a0, bb1);
            fma2(acc[0][2], a0, bb2); fma2(acc[0][3], a0, bb3);
            fma2(acc[1][0], a1, bb0); fma2(acc[1][1], a1, bb1);
            fma2(acc[1][2], a1, bb2); fma2(acc[1][3], a1, bb3);
            fma2(acc[2][0], a2, bb0); fma2(acc[2][1], a2, bb1);
            fma2(acc[2][2], a2, bb2); fma2(acc[2][3], a2, bb3);
            fma2(acc[3][0], a3, bb0); fma2(acc[3][1], a3, bb1);
            fma2(acc[3][2], a3, bb2); fma2(acc[3][3], a3, bb3);
        }
        if (kb < 7) { sts(cur ^ 1); __syncthreads(); }
    }

    float* up = g_up + ((size_t)(n * 32 + kc)) * C_ * C_;
#pragma unroll
    for (int p = 0; p < 4; p++) {
        int co0 = ty * 8 + 2 * p;
        float4 vl = make_float4(lo2(acc[p][0]), lo2(acc[p][1]),
                                lo2(acc[p][2]), lo2(acc[p][3]));
        float4 vh = make_float4(hi2(acc[p][0]), hi2(acc[p][1]),
                                hi2(acc[p][2]), hi2(acc[p][3]));
        *reinterpret_cast<float4*>(&up[co0 * 128 + tx * 4]) = vl;
        *reinterpret_cast<float4*>(&up[(co0 + 1) * 128 + tx * 4]) = vh;
    }
}

// K3b: reduce 32 split-K partials; write u transposed: g_u[n][ci][co]
__global__ void k3_red()
{
    int o = blockIdx.x * 256 + threadIdx.x;   // 131072
    int n = o >> 14, r = o & 16383;
    float s = 0.f;
#pragma unroll
    for (int kc = 0; kc < 32; kc++)
        s += g_up[(((size_t)(n * 32 + kc)) << 14) + r];
    int co = r >> 7, ci = r & 127;
    g_u[((size_t)n << 14) + ci * 128 + co] = s;
}

// ---------------------------------------------------------------------------
// K4: out = max( s3 * sum_ci u[n,co,ci]*t2[ci,p],  x[co,p] - 0.2*sum_jj t7 taps )
// double-buffered u chunks via cp.async; epilogue from smem t7 slab.
// ---------------------------------------------------------------------------
__global__ void k4_out(const float* __restrict__ x, const float* __restrict__ p1,
                       float* __restrict__ out)
{
    __shared__ __align__(16) float xs [128 * 64];     // t2[ci][w], later t7[co][w]
    __shared__ __align__(16) float as2[2][2048];      // u chunks [kk=ci][co]
    const int row = blockIdx.x, n = blockIdx.y;
    const int t = threadIdx.x;  // 128
    const int tx = t & 7, ty = t >> 3;
    const float* xn = x + (size_t)n * C_ * HW + row * 64;
    const float* un = g_u + ((size_t)n << 14);

#pragma unroll
    for (int r = 0; r < 4; r++)
        cpa16(s2u(&as2[0][r * 512 + t * 4]), &un[r * 512 + t * 4]);
    cpa_commit();

#pragma unroll
    for (int r = 0; r < 16; r++) {
        int idx4 = r * 512 + t * 4;
        int ci = idx4 >> 6, w = idx4 & 63;
        float s = 1.f + p1[ci * 64 + row];
        float4 v = *reinterpret_cast<const float4*>(&xn[(size_t)ci * HW + w]);
        v.x *= s; v.y *= s; v.z *= s; v.w *= s;
        *reinterpret_cast<float4*>(&xs[idx4]) = v;
    }

    u64 acc[4][8];
#pragma unroll
    for (int p = 0; p < 4; p++)
#pragma unroll
        for (int j = 0; j < 8; j++) acc[p][j] = 0ull;

    cpa_wait0();
    __syncthreads();

    for (int kb = 0; kb < 8; kb++) {
        const int cur = kb & 1;
        if (kb < 7) {
#pragma unroll
            for (int r = 0; r < 4; r++)
                cpa16(s2u(&as2[cur ^ 1][r * 512 + t * 4]),
                      &un[(kb + 1) * 2048 + r * 512 + t * 4]);
            cpa_commit();
        }
#pragma unroll
        for (int kk = 0; kk < 16; kk++) {
            int k = kb * 16 + kk;
            float4 b0 = *reinterpret_cast<const float4*>(&xs[k * 64 + tx * 8]);
            float4 b1 = *reinterpret_cast<const float4*>(&xs[k * 64 + tx * 8 + 4]);
            u64 a0 = *reinterpret_cast<const u64*>(&as2[cur][kk * 128 + ty * 8 + 0]);
            u64 a1 = *reinterpret_cast<const u64*>(&as2[cur][kk * 128 + ty * 8 + 2]);
            u64 a2 = *reinterpret_cast<const u64*>(&as2[cur][kk * 128 + ty * 8 + 4]);
            u64 a3 = *reinterpret_cast<const u64*>(&as2[cur][kk * 128 + ty * 8 + 6]);
            u64 bb[8];
            bb[0] = pack2(b0.x, b0.x); bb[1] = pack2(b0.y, b0.y);
            bb[2] = pack2(b0.z, b0.z); bb[3] = pack2(b0.w, b0.w);
            bb[4] = pack2(b1.x, b1.x); bb[5] = pack2(b1.y, b1.y);
            bb[6] = pack2(b1.z, b1.z); bb[7] = pack2(b1.w, b1.w);
#pragma unroll
            for (int j = 0; j < 8; j++) {
                fma2(acc[0][j], a0, bb[j]);
                fma2(acc[1][j], a1, bb[j]);
                fma2(acc[2][j], a2, bb[j]);
                fma2(acc[3][j], a3, bb[j]);
            }
        }
        if (kb < 7) { cpa_wait0(); __syncthreads(); }
    }

    // epilogue: reuse xs for t7[n,:,row,:]
    __syncthreads();
#pragma unroll
    for (int r = 0; r < 16; r++) {
        int idx4 = r * 512 + t * 4;
        int ci = idx4 >> 6, w = idx4 & 63;
        *reinterpret_cast<float4*>(&xs[idx4]) =
            *reinterpret_cast<const float4*>(
                &g_t7[((size_t)n * C_ + ci) * HW + row * 64 + w]);
    }
    __syncthreads();

    const float s3 = 0.01928793f;    // 1/sqrt(2688)
#pragma unroll
    for (int p = 0; p < 4; p++) {
#pragma unroll
        for (int half = 0; half < 2; half++) {
            int co = ty * 8 + 2 * p + half;
            const float* xr = xn + (size_t)co * HW;
            float4 xv0 = *reinterpret_cast<const float4*>(&xr[tx * 8]);
            float4 xv1 = *reinterpret_cast<const float4*>(&xr[tx * 8 + 4]);
            float xv[8] = {xv0.x, xv0.y, xv0.z, xv0.w, xv1.x, xv1.y, xv1.z, xv1.w};
            float res[8];
#pragma unroll
            for (int j = 0; j < 8; j++) {
                int pp = tx * 8 + j;
                float a = half ? hi2(acc[p][j]) : lo2(acc[p][j]);
                float sum = 0.f;
#pragma unroll
                for (int jj = 0; jj < 5; jj++) {
                    int wp = pp + 3 * jj - 6;
                    if ((unsigned)wp < 64u) sum += xs[co * 64 + wp];
                }
                float t12 = xv[j] - 0.2f * sum;
                res[j] = fmaxf(s3 * a, t12);
            }
            float* orow = out + ((size_t)n * C_ + co) * HW + row * 64;
            *reinterpret_cast<float4*>(&orow[tx * 8]) =
                make_float4(res[0], res[1], res[2], res[3]);
            *reinterpret_cast<float4*>(&orow[tx * 8 + 4]) =
                make_float4(res[4], res[5], res[6], res[7]);
        }
    }
}

// ---------------------------------------------------------------------------
extern "C" void kernel_launch(void* const* d_in, const int* in_sizes, int n_in,
                              void* d_out, int out_size)
{
    const float* x   = (const float*)d_in[0];   // (8,128,64,64)
    const float* p1w = (const float*)d_in[1];   // (1,128,64,1)
    const float* p7w = (const float*)d_in[2];   // (128,128)
    const float* p10 = (const float*)d_in[3];   // (2688,32)
    float* out = (float*)d_out;

    k0_tr  <<<64, 256>>>(p7w);
    k1_t7  <<<dim3(64, 8), 128>>>(x);
    k2_conv<<<dim3(16, 4, 8), 128>>>(x, p10);
    k3_part<<<dim3(32, 8), 512>>>(x, p1w);
    k3_red <<<512, 256>>>();
    k4_out <<<dim3(64, 8), 128>>>(x, p1w, out);
}

// round 13
// speedup vs baseline: 1.0362x; 1.0358x over previous
#include <cuda_runtime.h>
#include <cstdint>

#define N_ 8
#define C_ 128
#define H_ 64
#define W_ 64
#define HW 4096

typedef unsigned long long u64;

// scratch (no allocs allowed)
__device__ float g_t7 [N_ * C_ * HW];            // 16 MB
__device__ float g_y  [N_ * C_ * HW];            // 16 MB
__device__ float g_up [N_ * 32 * C_ * C_];       // 16 MB split-K partials
__device__ float g_u  [N_ * C_ * C_];            // 512 KB (transposed: [n][ci][co])
__device__ float g_p7t[C_ * C_];                 // p7 transposed [k][co]

// ---- helpers ---------------------------------------------------------------
__device__ __forceinline__ u64 pack2(float a, float b) {
    u64 r;
    asm("mov.b64 %0, {%1, %2};" : "=l"(r) : "f"(a), "f"(b));
    return r;
}
__device__ __forceinline__ void fma2(u64& d, u64 a, u64 b) {
    asm("fma.rn.f32x2 %0, %1, %2, %0;" : "+l"(d) : "l"(a), "l"(b));
}
__device__ __forceinline__ float lo2(u64 v) { return __uint_as_float((unsigned)v); }
__device__ __forceinline__ float hi2(u64 v) { return __uint_as_float((unsigned)(v >> 32)); }

__device__ __forceinline__ uint32_t s2u(const void* p) {
    return (uint32_t)__cvta_generic_to_shared(p);
}
__device__ __forceinline__ void cpa16(uint32_t dst, const void* src) {
    asm volatile("cp.async.cg.shared.global [%0], [%1], 16;" :: "r"(dst), "l"(src));
}
__device__ __forceinline__ void cpa4z(uint32_t dst, const void* src, bool p) {
    int sz = p ? 4 : 0;
    asm volatile("cp.async.ca.shared.global [%0], [%1], 4, %2;"
                 :: "r"(dst), "l"(src), "r"(sz));
}
__device__ __forceinline__ void cpa_commit() {
    asm volatile("cp.async.commit_group;" ::: "memory");
}
__device__ __forceinline__ void cpa_wait0() {
    asm volatile("cp.async.wait_group 0;" ::: "memory");
}
// cvt.rna.tf32.f32 needs a .b32 destination (ptxas rejects .f32 dst).
__device__ __forceinline__ uint32_t tf32_bits(float v) {
    uint32_t h;
    asm("cvt.rna.tf32.f32 %0, %1;" : "=r"(h) : "f"(v));
    return h;
}
// split v into tf32 hi (as float bits) and residual lo (as float bits)
__device__ __forceinline__ void tf32_split(float v, float& hf, float& lf) {
    uint32_t hb = tf32_bits(v);
    hf = __uint_as_float(hb);
    float lo = v - hf;
    lf = __uint_as_float(tf32_bits(lo));
}
// D += A(16x8,row) * B(8x8,col)  tf32
__device__ __forceinline__ void mma_tf32(float* c, uint32_t a0, uint32_t a1,
                                         uint32_t a2, uint32_t a3,
                                         uint32_t b0, uint32_t b1) {
    asm volatile(
        "mma.sync.aligned.m16n8k8.row.col.f32.tf32.tf32.f32 "
        "{%0,%1,%2,%3}, {%4,%5,%6,%7}, {%8,%9}, {%0,%1,%2,%3};"
        : "+f"(c[0]), "+f"(c[1]), "+f"(c[2]), "+f"(c[3])
        : "r"(a0), "r"(a1), "r"(a2), "r"(a3), "r"(b0), "r"(b1));
}

// ---------------------------------------------------------------------------
// K0: transpose p7 -> g_p7t[k][co]
// ---------------------------------------------------------------------------
__global__ void k0_tr(const float* __restrict__ p7)
{
    int idx = blockIdx.x * 256 + threadIdx.x;   // 16384
    int kk = idx >> 7, co = idx & 127;
    g_p7t[idx] = p7[co * 128 + kk];
}

// ---------------------------------------------------------------------------
// K1: t7[n,co,row,:] = sum_c p7[co,c] * relu(x[n,c,row,:])
// ---------------------------------------------------------------------------
__global__ void k1_t7(const float* __restrict__ x)
{
    __shared__ __align__(16) float xs [128 * 64];     // relu(x)[ci][w] 32KB
    __shared__ __align__(16) float as2[2][2048];      // p7t chunks [kk][co] 16KB
    const int row = blockIdx.x, n = blockIdx.y;
    const int t = threadIdx.x;
    const int tx = t & 7, ty = t >> 3;
    const float* xn = x + (size_t)n * C_ * HW + row * 64;

#pragma unroll
    for (int r = 0; r < 4; r++)
        cpa16(s2u(&as2[0][r * 512 + t * 4]), &g_p7t[r * 512 + t * 4]);
    cpa_commit();

#pragma unroll
    for (int r = 0; r < 16; r++) {
        int idx4 = r * 512 + t * 4;
        int ci = idx4 >> 6, w = idx4 & 63;
        float4 v = *reinterpret_cast<const float4*>(&xn[(size_t)ci * HW + w]);
        v.x = fmaxf(v.x, 0.f); v.y = fmaxf(v.y, 0.f);
        v.z = fmaxf(v.z, 0.f); v.w = fmaxf(v.w, 0.f);
        *reinterpret_cast<float4*>(&xs[idx4]) = v;
    }

    u64 acc[4][8];
#pragma unroll
    for (int p = 0; p < 4; p++)
#pragma unroll
        for (int j = 0; j < 8; j++) acc[p][j] = 0ull;

    cpa_wait0();
    __syncthreads();

    for (int kb = 0; kb < 8; kb++) {
        const int cur = kb & 1;
        if (kb < 7) {
#pragma unroll
            for (int r = 0; r < 4; r++)
                cpa16(s2u(&as2[cur ^ 1][r * 512 + t * 4]),
                      &g_p7t[(kb + 1) * 2048 + r * 512 + t * 4]);
            cpa_commit();
        }
#pragma unroll
        for (int kk = 0; kk < 16; kk++) {
            int k = kb * 16 + kk;
            float4 b0 = *reinterpret_cast<const float4*>(&xs[k * 64 + tx * 8]);
            float4 b1 = *reinterpret_cast<const float4*>(&xs[k * 64 + tx * 8 + 4]);
            u64 a0 = *reinterpret_cast<const u64*>(&as2[cur][kk * 128 + ty * 8 + 0]);
            u64 a1 = *reinterpret_cast<const u64*>(&as2[cur][kk * 128 + ty * 8 + 2]);
            u64 a2 = *reinterpret_cast<const u64*>(&as2[cur][kk * 128 + ty * 8 + 4]);
            u64 a3 = *reinterpret_cast<const u64*>(&as2[cur][kk * 128 + ty * 8 + 6]);
            u64 bb[8];
            bb[0] = pack2(b0.x, b0.x); bb[1] = pack2(b0.y, b0.y);
            bb[2] = pack2(b0.z, b0.z); bb[3] = pack2(b0.w, b0.w);
            bb[4] = pack2(b1.x, b1.x); bb[5] = pack2(b1.y, b1.y);
            bb[6] = pack2(b1.z, b1.z); bb[7] = pack2(b1.w, b1.w);
#pragma unroll
            for (int j = 0; j < 8; j++) {
                fma2(acc[0][j], a0, bb[j]);
                fma2(acc[1][j], a1, bb[j]);
                fma2(acc[2][j], a2, bb[j]);
                fma2(acc[3][j], a3, bb[j]);
            }
        }
        if (kb < 7) { cpa_wait0(); __syncthreads(); }
    }

    float* t7n = g_t7 + (size_t)n * C_ * HW + row * 64;
#pragma unroll
    for (int p = 0; p < 4; p++) {
        int co0 = ty * 8 + 2 * p;
#pragma unroll
        for (int jq = 0; jq < 2; jq++) {
            float4 vl = make_float4(lo2(acc[p][jq*4+0]), lo2(acc[p][jq*4+1]),
                                    lo2(acc[p][jq*4+2]), lo2(acc[p][jq*4+3]));
            float4 vh = make_float4(hi2(acc[p][jq*4+0]), hi2(acc[p][jq*4+1]),
                                    hi2(acc[p][jq*4+2]), hi2(acc[p][jq*4+3]));
            *reinterpret_cast<float4*>(&t7n[(size_t)co0 * HW + tx * 8 + jq * 4]) = vl;
            *reinterpret_cast<float4*>(&t7n[(size_t)(co0 + 1) * HW + tx * 8 + jq * 4]) = vh;
        }
    }
}

// ---------------------------------------------------------------------------
// K2: grouped 3x7 conv, f32x2 along cin; ci-chunks of 4, double-buffered via
// cp.async (x halo gets zero-fill).
// ---------------------------------------------------------------------------
__global__ void __launch_bounds__(128) k2_conv(const float* __restrict__ x,
                                               const float* __restrict__ p10)
{
    __shared__ __align__(16) float xs[2][1520];   // [ci4][hh10][ww38]
    __shared__ __align__(16) float ws[2][2688];   // [ci4][k21][cin32]
    const int tile = blockIdx.x;        // 0..15
    const int g = blockIdx.y, n = blockIdx.z;
    const int h0 = (tile >> 1) * 8, w0 = (tile & 1) * 32;
    const int t = threadIdx.x;          // 128
    const int wl = t & 31, oct = t >> 5;

    auto load_chunk = [&](int cc, int b) {
        for (int idx = t; idx < 1520; idx += 128) {
            int ci = idx / 380;
            int rem = idx - ci * 380;
            int hh = rem / 38, ww = rem - hh * 38;
            int hg = h0 - 1 + hh, wg = w0 - 3 + ww;
            bool p = ((unsigned)hg < 64u) && ((unsigned)wg < 64u);
            const float* src = p
                ? &x[(((size_t)n * C_ + g * 32 + cc * 4 + ci) * 64 + hg) * 64 + wg]
                : x;
            cpa4z(s2u(&xs[b][idx]), src, p);
        }
        const float* wsrc = p10 + (size_t)(g * 32 + cc * 4) * 672;
        for (int i4 = t * 4; i4 < 2688; i4 += 512)
            cpa16(s2u(&ws[b][i4]), wsrc + i4);
        cpa_commit();
    };

    u64 acc[4][8];
#pragma unroll
    for (int q = 0; q < 4; q++)
#pragma unroll
        for (int hh = 0; hh < 8; hh++) acc[q][hh] = 0ull;

    load_chunk(0, 0);
    cpa_wait0();
    __syncthreads();

    for (int cc = 0; cc < 8; cc++) {
        const int cur = cc & 1;
        if (cc < 7) load_chunk(cc + 1, cur ^ 1);

#pragma unroll 1
        for (int ci = 0; ci < 4; ci++) {
#pragma unroll
            for (int k = 0; k < 21; k++) {
                const int di = k / 7, dj = k - di * 7;
                const float* wp = &ws[cur][(ci * 21 + k) * 32 + oct * 8];
                u64 w0p = *reinterpret_cast<const u64*>(wp + 0);
                u64 w1p = *reinterpret_cast<const u64*>(wp + 2);
                u64 w2p = *reinterpret_cast<const u64*>(wp + 4);
                u64 w3p = *reinterpret_cast<const u64*>(wp + 6);
                const float* xr = &xs[cur][(ci * 10 + di) * 38 + wl + dj];
#pragma unroll
                for (int hh = 0; hh < 8; hh++) {
                    float xv = xr[hh * 38];
                    u64 xx = pack2(xv, xv);
                    fma2(acc[0][hh], w0p, xx);
                    fma2(acc[1][hh], w1p, xx);
                    fma2(acc[2][hh], w2p, xx);
                    fma2(acc[3][hh], w3p, xx);
                }
            }
        }
        if (cc < 7) { cpa_wait0(); __syncthreads(); }
    }

#pragma unroll
    for (int q = 0; q < 4; q++)
#pragma unroll
        for (int hh = 0; hh < 8; hh++) {
            int cin0 = g * 32 + oct * 8 + 2 * q;
            g_y[(((size_t)n * C_ + cin0) * 64 + h0 + hh) * 64 + w0 + wl] = lo2(acc[q][hh]);
            g_y[(((size_t)n * C_ + cin0 + 1) * 64 + h0 + hh) * 64 + w0 + wl] = hi2(acc[q][hh]);
        }
}

// ---------------------------------------------------------------------------
// K3 (mma.sync tf32, 3-pass hi/lo): per (n,kc) CTA computes the 128x128x128
// partial  u_part[co][ci] = (1/64) sum_p t1[co,p] * y[ci,p]
// 256 threads = 8 warps; warp w owns co rows [w*16, w*16+16), all 128 ci.
// K processed in 4 sub-chunks of 32. Smem: Ah/Al/Bh/Bl 128x32, pitch 36.
// ---------------------------------------------------------------------------
#define K3_PITCH 36
__global__ void __launch_bounds__(256) k3_mma(const float* __restrict__ x,
                                              const float* __restrict__ p1)
{
    extern __shared__ __align__(16) float sm[];
    float* Ah = sm;                    // 128*36
    float* Al = Ah + 128 * K3_PITCH;
    float* Bh = Al + 128 * K3_PITCH;
    float* Bl = Bh + 128 * K3_PITCH;

    const int t = threadIdx.x;
    const int kc = blockIdx.x, n = blockIdx.y;
    const int wid = t >> 5, lane = t & 31;
    const int g4 = lane >> 2, l4 = lane & 3;
    const int wco = wid * 16;

    const int p0 = kc * 128;
    const float* xn = x   + (size_t)n * C_ * HW;
    const float* yn = g_y + (size_t)n * C_ * HW;

    float c[16][4];
#pragma unroll
    for (int i = 0; i < 16; i++)
#pragma unroll
        for (int j = 0; j < 4; j++) c[i][j] = 0.f;

    const int frow = t >> 1;              // fill row 0..127
    const int fch  = (t & 1) * 16;        // col half

    for (int sub = 0; sub < 4; sub++) {
        const int pb = p0 + sub * 32;
        const int h = pb >> 6;
        const float sA = p1[frow * 64 + h] * (1.f / 64.f);
        const float* xr = xn + (size_t)frow * HW + pb + fch;
        const float* yr = yn + (size_t)frow * HW + pb + fch;

        if (sub) __syncthreads();         // all consumers done with prev tiles
#pragma unroll
        for (int q = 0; q < 4; q++) {
            float4 va = *reinterpret_cast<const float4*>(xr + q * 4);
            va.x *= sA; va.y *= sA; va.z *= sA; va.w *= sA;
            float4 vh, vl;
            tf32_split(va.x, vh.x, vl.x);
            tf32_split(va.y, vh.y, vl.y);
            tf32_split(va.z, vh.z, vl.z);
            tf32_split(va.w, vh.w, vl.w);
            *reinterpret_cast<float4*>(&Ah[frow * K3_PITCH + fch + q * 4]) = vh;
            *reinterpret_cast<float4*>(&Al[frow * K3_PITCH + fch + q * 4]) = vl;
            float4 vb = *reinterpret_cast<const float4*>(yr + q * 4);
            tf32_split(vb.x, vh.x, vl.x);
            tf32_split(vb.y, vh.y, vl.y);
            tf32_split(vb.z, vh.z, vl.z);
            tf32_split(vb.w, vh.w, vl.w);
            *reinterpret_cast<float4*>(&Bh[frow * K3_PITCH + fch + q * 4]) = vh;
            *reinterpret_cast<float4*>(&Bl[frow * K3_PITCH + fch + q * 4]) = vl;
        }
        __syncthreads();

#pragma unroll
        for (int ks = 0; ks < 4; ks++) {
            const int k0 = ks * 8;
            const float* Ab = &Ah[(wco + g4) * K3_PITCH + k0 + l4];
            const float* Alb = &Al[(wco + g4) * K3_PITCH + k0 + l4];
            uint32_t ah0 = __float_as_uint(Ab[0]);
            uint32_t ah1 = __float_as_uint(Ab[8 * K3_PITCH]);
            uint32_t ah2 = __float_as_uint(Ab[4]);
            uint32_t ah3 = __float_as_uint(Ab[8 * K3_PITCH + 4]);
            uint32_t al0 = __float_as_uint(Alb[0]);
            uint32_t al1 = __float_as_uint(Alb[8 * K3_PITCH]);
            uint32_t al2 = __float_as_uint(Alb[4]);
            uint32_t al3 = __float_as_uint(Alb[8 * K3_PITCH + 4]);
#pragma unroll
            for (int tile = 0; tile < 16; tile++) {
                const float* Bb = &Bh[(tile * 8 + g4) * K3_PITCH + k0 + l4];
                const float* Blb = &Bl[(tile * 8 + g4) * K3_PITCH + k0 + l4];
                uint32_t bh0 = __float_as_uint(Bb[0]);
                uint32_t bh1 = __float_as_uint(Bb[4]);
                uint32_t bl0 = __float_as_uint(Blb[0]);
                uint32_t bl1 = __float_as_uint(Blb[4]);
                mma_tf32(c[tile], ah0, ah1, ah2, ah3, bh0, bh1);
                mma_tf32(c[tile], ah0, ah1, ah2, ah3, bl0, bl1);
                mma_tf32(c[tile], al0, al1, al2, al3, bh0, bh1);
            }
        }
    }

    // epilogue: c layout -> up[co][ci]
    float* up = g_up + ((size_t)(n * 32 + kc)) * C_ * C_;
    const int r0 = wco + g4, r1 = wco + g4 + 8;
#pragma unroll
    for (int tile = 0; tile < 16; tile++) {
        const int cix = tile * 8 + l4 * 2;
        *reinterpret_cast<float2*>(&up[(size_t)r0 * 128 + cix]) =
            make_float2(c[tile][0], c[tile][1]);
        *reinterpret_cast<float2*>(&up[(size_t)r1 * 128 + cix]) =
            make_float2(c[tile][2], c[tile][3]);
    }
}

// K3b: reduce 32 split-K partials; write u transposed: g_u[n][ci][co]
__global__ void k3_red()
{
    int o = blockIdx.x * 256 + threadIdx.x;   // 131072
    int n = o >> 14, r = o & 16383;
    float s = 0.f;
#pragma unroll
    for (int kc = 0; kc < 32; kc++)
        s += g_up[(((size_t)(n * 32 + kc)) << 14) + r];
    int co = r >> 7, ci = r & 127;
    g_u[((size_t)n << 14) + ci * 128 + co] = s;
}

// ---------------------------------------------------------------------------
// K4: out = max( s3 * sum_ci u[n,co,ci]*t2[ci,p],  x[co,p] - 0.2*sum_jj t7 taps )
// ---------------------------------------------------------------------------
__global__ void k4_out(const float* __restrict__ x, const float* __restrict__ p1,
                       float* __restrict__ out)
{
    __shared__ __align__(16) float xs [128 * 64];     // t2[ci][w], later t7[co][w]
    __shared__ __align__(16) float as2[2][2048];      // u chunks [kk=ci][co]
    const int row = blockIdx.x, n = blockIdx.y;
    const int t = threadIdx.x;  // 128
    const int tx = t & 7, ty = t >> 3;
    const float* xn = x + (size_t)n * C_ * HW + row * 64;
    const float* un = g_u + ((size_t)n << 14);

#pragma unroll
    for (int r = 0; r < 4; r++)
        cpa16(s2u(&as2[0][r * 512 + t * 4]), &un[r * 512 + t * 4]);
    cpa_commit();

#pragma unroll
    for (int r = 0; r < 16; r++) {
        int idx4 = r * 512 + t * 4;
        int ci = idx4 >> 6, w = idx4 & 63;
        float s = 1.f + p1[ci * 64 + row];
        float4 v = *reinterpret_cast<const float4*>(&xn[(size_t)ci * HW + w]);
        v.x *= s; v.y *= s; v.z *= s; v.w *= s;
        *reinterpret_cast<float4*>(&xs[idx4]) = v;
    }

    u64 acc[4][8];
#pragma unroll
    for (int p = 0; p < 4; p++)
#pragma unroll
        for (int j = 0; j < 8; j++) acc[p][j] = 0ull;

    cpa_wait0();
    __syncthreads();

    for (int kb = 0; kb < 8; kb++) {
        const int cur = kb & 1;
        if (kb < 7) {
#pragma unroll
            for (int r = 0; r < 4; r++)
                cpa16(s2u(&as2[cur ^ 1][r * 512 + t * 4]),
                      &un[(kb + 1) * 2048 + r * 512 + t * 4]);
            cpa_commit();
        }
#pragma unroll
        for (int kk = 0; kk < 16; kk++) {
            int k = kb * 16 + kk;
            float4 b0 = *reinterpret_cast<const float4*>(&xs[k * 64 + tx * 8]);
            float4 b1 = *reinterpret_cast<const float4*>(&xs[k * 64 + tx * 8 + 4]);
            u64 a0 = *reinterpret_cast<const u64*>(&as2[cur][kk * 128 + ty * 8 + 0]);
            u64 a1 = *reinterpret_cast<const u64*>(&as2[cur][kk * 128 + ty * 8 + 2]);
            u64 a2 = *reinterpret_cast<const u64*>(&as2[cur][kk * 128 + ty * 8 + 4]);
            u64 a3 = *reinterpret_cast<const u64*>(&as2[cur][kk * 128 + ty * 8 + 6]);
            u64 bb[8];
            bb[0] = pack2(b0.x, b0.x); bb[1] = pack2(b0.y, b0.y);
            bb[2] = pack2(b0.z, b0.z); bb[3] = pack2(b0.w, b0.w);
            bb[4] = pack2(b1.x, b1.x); bb[5] = pack2(b1.y, b1.y);
            bb[6] = pack2(b1.z, b1.z); bb[7] = pack2(b1.w, b1.w);
#pragma unroll
            for (int j = 0; j < 8; j++) {
                fma2(acc[0][j], a0, bb[j]);
                fma2(acc[1][j], a1, bb[j]);
                fma2(acc[2][j], a2, bb[j]);
                fma2(acc[3][j], a3, bb[j]);
            }
        }
        if (kb < 7) { cpa_wait0(); __syncthreads(); }
    }

    // epilogue: reuse xs for t7[n,:,row,:]
    __syncthreads();
#pragma unroll
    for (int r = 0; r < 16; r++) {
        int idx4 = r * 512 + t * 4;
        int ci = idx4 >> 6, w = idx4 & 63;
        *reinterpret_cast<float4*>(&xs[idx4]) =
            *reinterpret_cast<const float4*>(
                &g_t7[((size_t)n * C_ + ci) * HW + row * 64 + w]);
    }
    __syncthreads();

    const float s3 = 0.01928793f;    // 1/sqrt(2688)
#pragma unroll
    for (int p = 0; p < 4; p++) {
#pragma unroll
        for (int half = 0; half < 2; half++) {
            int co = ty * 8 + 2 * p + half;
            const float* xr = xn + (size_t)co * HW;
            float4 xv0 = *reinterpret_cast<const float4*>(&xr[tx * 8]);
            float4 xv1 = *reinterpret_cast<const float4*>(&xr[tx * 8 + 4]);
            float xv[8] = {xv0.x, xv0.y, xv0.z, xv0.w, xv1.x, xv1.y, xv1.z, xv1.w};
            float res[8];
#pragma unroll
            for (int j = 0; j < 8; j++) {
                int pp = tx * 8 + j;
                float a = half ? hi2(acc[p][j]) : lo2(acc[p][j]);
                float sum = 0.f;
#pragma unroll
                for (int jj = 0; jj < 5; jj++) {
                    int wp = pp + 3 * jj - 6;
                    if ((unsigned)wp < 64u) sum += xs[co * 64 + wp];
                }
                float t12 = xv[j] - 0.2f * sum;
                res[j] = fmaxf(s3 * a, t12);
            }
            float* orow = out + ((size_t)n * C_ + co) * HW + row * 64;
            *reinterpret_cast<float4*>(&orow[tx * 8]) =
                make_float4(res[0], res[1], res[2], res[3]);
            *reinterpret_cast<float4*>(&orow[tx * 8 + 4]) =
                make_float4(res[4], res[5], res[6], res[7]);
        }
    }
}

// ---------------------------------------------------------------------------
extern "C" void kernel_launch(void* const* d_in, const int* in_sizes, int n_in,
                              void* d_out, int out_size)
{
    const float* x   = (const float*)d_in[0];   // (8,128,64,64)
    const float* p1w = (const float*)d_in[1];   // (1,128,64,1)
    const float* p7w = (const float*)d_in[2];   // (128,128)
    const float* p10 = (const float*)d_in[3];   // (2688,32)
    float* out = (float*)d_out;

    const int k3_smem = 4 * 128 * K3_PITCH * 4;     // 73728 B dynamic
    cudaFuncSetAttribute(k3_mma, cudaFuncAttributeMaxDynamicSharedMemorySize, k3_smem);

    k0_tr  <<<64, 256>>>(p7w);
    k1_t7  <<<dim3(64, 8), 128>>>(x);
    k2_conv<<<dim3(16, 4, 8), 128>>>(x, p10);
    k3_mma <<<dim3(32, 8), 256, k3_smem>>>(x, p1w);
    k3_red <<<512, 256>>>();
    k4_out <<<dim3(64, 8), 128>>>(x, p1w, out);
}

// round 15
// speedup vs baseline: 1.0440x; 1.0075x over previous
#include <cuda_runtime.h>
#include <cstdint>

#define N_ 8
#define C_ 128
#define H_ 64
#define W_ 64
#define HW 4096

typedef unsigned long long u64;

// scratch (no allocs allowed)
__device__ float g_t7 [N_ * C_ * HW];            // 16 MB
__device__ float g_y  [N_ * C_ * HW];            // 16 MB
__device__ float g_up [N_ * 32 * C_ * C_];       // 16 MB split-K partials
__device__ float g_u  [N_ * C_ * C_];            // 512 KB (transposed: [n][ci][co])
__device__ float g_p7h[C_ * C_];                 // p7 tf32-hi  [co][ci]
__device__ float g_p7l[C_ * C_];                 // p7 residual [co][ci]

// ---- helpers ---------------------------------------------------------------
__device__ __forceinline__ u64 pack2(float a, float b) {
    u64 r;
    asm("mov.b64 %0, {%1, %2};" : "=l"(r) : "f"(a), "f"(b));
    return r;
}
__device__ __forceinline__ void fma2(u64& d, u64 a, u64 b) {
    asm("fma.rn.f32x2 %0, %1, %2, %0;" : "+l"(d) : "l"(a), "l"(b));
}
__device__ __forceinline__ float lo2(u64 v) { return __uint_as_float((unsigned)v); }
__device__ __forceinline__ float hi2(u64 v) { return __uint_as_float((unsigned)(v >> 32)); }

__device__ __forceinline__ uint32_t s2u(const void* p) {
    return (uint32_t)__cvta_generic_to_shared(p);
}
__device__ __forceinline__ void cpa16(uint32_t dst, const void* src) {
    asm volatile("cp.async.cg.shared.global [%0], [%1], 16;" :: "r"(dst), "l"(src));
}
__device__ __forceinline__ void cpa4z(uint32_t dst, const void* src, bool p) {
    int sz = p ? 4 : 0;
    asm volatile("cp.async.ca.shared.global [%0], [%1], 4, %2;"
                 :: "r"(dst), "l"(src), "r"(sz));
}
__device__ __forceinline__ void cpa_commit() {
    asm volatile("cp.async.commit_group;" ::: "memory");
}
__device__ __forceinline__ void cpa_wait0() {
    asm volatile("cp.async.wait_group 0;" ::: "memory");
}
// cvt.rna.tf32.f32 needs a .b32 destination (ptxas rejects .f32 dst).
__device__ __forceinline__ uint32_t tf32_bits(float v) {
    uint32_t h;
    asm("cvt.rna.tf32.f32 %0, %1;" : "=r"(h) : "f"(v));
    return h;
}
__device__ __forceinline__ void tf32_split(float v, float& hf, float& lf) {
    uint32_t hb = tf32_bits(v);
    hf = __uint_as_float(hb);
    float lo = v - hf;
    lf = __uint_as_float(tf32_bits(lo));
}
// D += A(16x8,row) * B(8x8,col)  tf32
__device__ __forceinline__ void mma_tf32(float* c, uint32_t a0, uint32_t a1,
                                         uint32_t a2, uint32_t a3,
                                         uint32_t b0, uint32_t b1) {
    asm volatile(
        "mma.sync.aligned.m16n8k8.row.col.f32.tf32.tf32.f32 "
        "{%0,%1,%2,%3}, {%4,%5,%6,%7}, {%8,%9}, {%0,%1,%2,%3};"
        : "+f"(c[0]), "+f"(c[1]), "+f"(c[2]), "+f"(c[3])
        : "r"(a0), "r"(a1), "r"(a2), "r"(a3), "r"(b0), "r"(b1));
}

// ---------------------------------------------------------------------------
// K0: pre-split p7 into tf32 hi/lo ([co][ci] row-major, no transpose)
// ---------------------------------------------------------------------------
__global__ void k0_prep(const float* __restrict__ p7)
{
    int idx = blockIdx.x * 256 + threadIdx.x;   // 16384
    float h, l;
    tf32_split(p7[idx], h, l);
    g_p7h[idx] = h;
    g_p7l[idx] = l;
}

// ---------------------------------------------------------------------------
// K1 (mma.sync tf32, pipelined): t7[n,co,p0+0..128) = sum_ci p7[co,ci]*relu(x[n,ci,p])
// 256 threads, 8 warps; warp w: co rows [w*16, w*16+16), all 128 p (16 tiles).
// K=128 ci in 8 subs of 16, double-buffered. A via cp.async (pre-split),
// B split at fill. Smem floats: Ah[2][128*20]@0, Al@5120, Bh[2][16*136]@10240,
// Bl@14592; total 18944 floats = 75776 B.
// ---------------------------------------------------------------------------
__global__ void __launch_bounds__(256) k1_mma(const float* __restrict__ x)
{
    extern __shared__ __align__(16) float sm[];
    const int t = threadIdx.x;
    const int pt = blockIdx.x, n = blockIdx.y;
    const int p0 = pt * 128;
    const int wid = t >> 5, lane = t & 31;
    const int g4 = lane >> 2, l4 = lane & 3;
    const int wco = wid * 16;
    const float* xn = x + (size_t)n * C_ * HW;

    float c[16][4];
#pragma unroll
    for (int i = 0; i < 16; i++)
#pragma unroll
        for (int j = 0; j < 4; j++) c[i][j] = 0.f;

    float4 bx[2];
    auto ldgB = [&](int sub) {
        const int ci0 = sub * 16;
#pragma unroll
        for (int k = 0; k < 2; k++) {
            int fi = t + k * 256;
            int ci = fi >> 5, pq = (fi & 31) * 4;
            bx[k] = *reinterpret_cast<const float4*>(
                &xn[(size_t)(ci0 + ci) * HW + p0 + pq]);
        }
    };
    auto cpaA = [&](int sub, int b) {
        const int ci0 = sub * 16;
        float* Ah = sm + b * 2560;
        float* Al = sm + 5120 + b * 2560;
#pragma unroll
        for (int k = 0; k < 2; k++) {
            int fi = t + k * 256;
            int co = fi >> 2, q = (fi & 3) * 4;
            cpa16(s2u(&Ah[co * 20 + q]), &g_p7h[co * 128 + ci0 + q]);
            cpa16(s2u(&Al[co * 20 + q]), &g_p7l[co * 128 + ci0 + q]);
        }
        cpa_commit();
    };
    auto stsB = [&](int b) {
        float* Bh = sm + 10240 + b * 2176;
        float* Bl = sm + 14592 + b * 2176;
#pragma unroll
        for (int k = 0; k < 2; k++) {
            int fi = t + k * 256;
            int ci = fi >> 5, pq = (fi & 31) * 4;
            float4 vh, vl;
            tf32_split(fmaxf(bx[k].x, 0.f), vh.x, vl.x);
            tf32_split(fmaxf(bx[k].y, 0.f), vh.y, vl.y);
            tf32_split(fmaxf(bx[k].z, 0.f), vh.z, vl.z);
            tf32_split(fmaxf(bx[k].w, 0.f), vh.w, vl.w);
            *reinterpret_cast<float4*>(&Bh[ci * 136 + pq]) = vh;
            *reinterpret_cast<float4*>(&Bl[ci * 136 + pq]) = vl;
        }
    };

    ldgB(0);
    cpaA(0, 0);
    stsB(0);
    cpa_wait0();
    __syncthreads();

    for (int sub = 0; sub < 8; sub++) {
        const int cur = sub & 1;
        if (sub < 7) {
            ldgB(sub + 1);
            cpaA(sub + 1, cur ^ 1);
        }
        const float* Ah = sm + cur * 2560;
        const float* Al = sm + 5120 + cur * 2560;
        const float* Bh = sm + 10240 + cur * 2176;
        const float* Bl = sm + 14592 + cur * 2176;
#pragma unroll
        for (int ks = 0; ks < 2; ks++) {
            const int k0 = ks * 8;
            const float* Ab  = &Ah[(wco + g4) * 20 + k0 + l4];
            const float* Alb = &Al[(wco + g4) * 20 + k0 + l4];
            uint32_t ah0 = __float_as_uint(Ab[0]);
            uint32_t ah1 = __float_as_uint(Ab[8 * 20]);
            uint32_t ah2 = __float_as_uint(Ab[4]);
            uint32_t ah3 = __float_as_uint(Ab[8 * 20 + 4]);
            uint32_t al0 = __float_as_uint(Alb[0]);
            uint32_t al1 = __float_as_uint(Alb[8 * 20]);
            uint32_t al2 = __float_as_uint(Alb[4]);
            uint32_t al3 = __float_as_uint(Alb[8 * 20 + 4]);
#pragma unroll
            for (int tile = 0; tile < 16; tile++) {
                const float* Bb  = &Bh[(k0 + l4) * 136 + tile * 8 + g4];
                const float* Blb = &Bl[(k0 + l4) * 136 + tile * 8 + g4];
                uint32_t bh0 = __float_as_uint(Bb[0]);
                uint32_t bh1 = __float_as_uint(Bb[4 * 136]);
                uint32_t bl0 = __float_as_uint(Blb[0]);
                uint32_t bl1 = __float_as_uint(Blb[4 * 136]);
                mma_tf32(c[tile], ah0, ah1, ah2, ah3, bh0, bh1);
                mma_tf32(c[tile], ah0, ah1, ah2, ah3, bl0, bl1);
                mma_tf32(c[tile], al0, al1, al2, al3, bh0, bh1);
            }
        }
        if (sub < 7) {
            stsB(cur ^ 1);
            cpa_wait0();
            __syncthreads();
        }
    }

    float* t7n = g_t7 + (size_t)n * C_ * HW;
    const int r0 = wco + g4, r1 = wco + g4 + 8;
#pragma unroll
    for (int tile = 0; tile < 16; tile++) {
        const int p = p0 + tile * 8 + l4 * 2;
        *reinterpret_cast<float2*>(&t7n[(size_t)r0 * HW + p]) =
            make_float2(c[tile][0], c[tile][1]);
        *reinterpret_cast<float2*>(&t7n[(size_t)r1 * HW + p]) =
            make_float2(c[tile][2], c[tile][3]);
    }
}

// ---------------------------------------------------------------------------
// K2: grouped 3x7 conv, f32x2 along cin; ci-chunks of 4, double-buffered via
// cp.async (x halo gets zero-fill).
// ---------------------------------------------------------------------------
__global__ void __launch_bounds__(128) k2_conv(const float* __restrict__ x,
                                               const float* __restrict__ p10)
{
    __shared__ __align__(16) float xs[2][1520];   // [ci4][hh10][ww38]
    __shared__ __align__(16) float ws[2][2688];   // [ci4][k21][cin32]
    const int tile = blockIdx.x;        // 0..15
    const int g = blockIdx.y, n = blockIdx.z;
    const int h0 = (tile >> 1) * 8, w0 = (tile & 1) * 32;
    const int t = threadIdx.x;          // 128
    const int wl = t & 31, oct = t >> 5;

    auto load_chunk = [&](int cc, int b) {
        for (int idx = t; idx < 1520; idx += 128) {
            int ci = idx / 380;
            int rem = idx - ci * 380;
            int hh = rem / 38, ww = rem - hh * 38;
            int hg = h0 - 1 + hh, wg = w0 - 3 + ww;
            bool p = ((unsigned)hg < 64u) && ((unsigned)wg < 64u);
            const float* src = p
                ? &x[(((size_t)n * C_ + g * 32 + cc * 4 + ci) * 64 + hg) * 64 + wg]
                : x;
            cpa4z(s2u(&xs[b][idx]), src, p);
        }
        const float* wsrc = p10 + (size_t)(g * 32 + cc * 4) * 672;
        for (int i4 = t * 4; i4 < 2688; i4 += 512)
            cpa16(s2u(&ws[b][i4]), wsrc + i4);
        cpa_commit();
    };

    u64 acc[4][8];
#pragma unroll
    for (int q = 0; q < 4; q++)
#pragma unroll
        for (int hh = 0; hh < 8; hh++) acc[q][hh] = 0ull;

    load_chunk(0, 0);
    cpa_wait0();
    __syncthreads();

    for (int cc = 0; cc < 8; cc++) {
        const int cur = cc & 1;
        if (cc < 7) load_chunk(cc + 1, cur ^ 1);

#pragma unroll 1
        for (int ci = 0; ci < 4; ci++) {
#pragma unroll
            for (int k = 0; k < 21; k++) {
                const int di = k / 7, dj = k - di * 7;
                const float* wp = &ws[cur][(ci * 21 + k) * 32 + oct * 8];
                u64 w0p = *reinterpret_cast<const u64*>(wp + 0);
                u64 w1p = *reinterpret_cast<const u64*>(wp + 2);
                u64 w2p = *reinterpret_cast<const u64*>(wp + 4);
                u64 w3p = *reinterpret_cast<const u64*>(wp + 6);
                const float* xr = &xs[cur][(ci * 10 + di) * 38 + wl + dj];
#pragma unroll
                for (int hh = 0; hh < 8; hh++) {
                    float xv = xr[hh * 38];
                    u64 xx = pack2(xv, xv);
                    fma2(acc[0][hh], w0p, xx);
                    fma2(acc[1][hh], w1p, xx);
                    fma2(acc[2][hh], w2p, xx);
                    fma2(acc[3][hh], w3p, xx);
                }
            }
        }
        if (cc < 7) { cpa_wait0(); __syncthreads(); }
    }

#pragma unroll
    for (int q = 0; q < 4; q++)
#pragma unroll
        for (int hh = 0; hh < 8; hh++) {
            int cin0 = g * 32 + oct * 8 + 2 * q;
            g_y[(((size_t)n * C_ + cin0) * 64 + h0 + hh) * 64 + w0 + wl] = lo2(acc[q][hh]);
            g_y[(((size_t)n * C_ + cin0 + 1) * 64 + h0 + hh) * 64 + w0 + wl] = hi2(acc[q][hh]);
        }
}

// ---------------------------------------------------------------------------
// K3 (mma.sync tf32, pipelined): per (n,kc) CTA, 128x128x128 partial
// u_part[co][ci] = (1/64) sum_p t1[co,p] * y[ci,p]
// 8 subs of 16 p, double-buffered. Smem floats: Ah[2][128*20]@0, Al@5120,
// Bh[2][128*20]@10240, Bl@15360; total 20480 floats = 81920 B.
// ---------------------------------------------------------------------------
__global__ void __launch_bounds__(256) k3_mma(const float* __restrict__ x,
                                              const float* __restrict__ p1)
{
    extern __shared__ __align__(16) float sm[];
    const int t = threadIdx.x;
    const int kc = blockIdx.x, n = blockIdx.y;
    const int wid = t >> 5, lane = t & 31;
    const int g4 = lane >> 2, l4 = lane & 3;
    const int wco = wid * 16;

    const int p0 = kc * 128;
    const float* xn = x   + (size_t)n * C_ * HW;
    const float* yn = g_y + (size_t)n * C_ * HW;

    float c[16][4];
#pragma unroll
    for (int i = 0; i < 16; i++)
#pragma unroll
        for (int j = 0; j < 4; j++) c[i][j] = 0.f;

    float4 ax[2], ay[2];
    float sA[2];
    auto ldg = [&](int sub) {
        const int pb = p0 + sub * 16;
        const int h = pb >> 6;
#pragma unroll
        for (int k = 0; k < 2; k++) {
            int fi = t + k * 256;
            int row = fi >> 2, q = (fi & 3) * 4;
            sA[k] = p1[row * 64 + h] * (1.f / 64.f);
            ax[k] = *reinterpret_cast<const float4*>(&xn[(size_t)row * HW + pb + q]);
            ay[k] = *reinterpret_cast<const float4*>(&yn[(size_t)row * HW + pb + q]);
        }
    };
    auto sts = [&](int b) {
        float* Ah = sm + b * 2560;
        float* Al = sm + 5120 + b * 2560;
        float* Bh = sm + 10240 + b * 2560;
        float* Bl = sm + 15360 + b * 2560;
#pragma unroll
        for (int k = 0; k < 2; k++) {
            int fi = t + k * 256;
            int row = fi >> 2, q = (fi & 3) * 4;
            float4 vh, vl;
            tf32_split(sA[k] * ax[k].x, vh.x, vl.x);
            tf32_split(sA[k] * ax[k].y, vh.y, vl.y);
            tf32_split(sA[k] * ax[k].z, vh.z, vl.z);
            tf32_split(sA[k] * ax[k].w, vh.w, vl.w);
            *reinterpret_cast<float4*>(&Ah[row * 20 + q]) = vh;
            *reinterpret_cast<float4*>(&Al[row * 20 + q]) = vl;
            tf32_split(ay[k].x, vh.x, vl.x);
            tf32_split(ay[k].y, vh.y, vl.y);
            tf32_split(ay[k].z, vh.z, vl.z);
            tf32_split(ay[k].w, vh.w, vl.w);
            *reinterpret_cast<float4*>(&Bh[row * 20 + q]) = vh;
            *reinterpret_cast<float4*>(&Bl[row * 20 + q]) = vl;
        }
    };

    ldg(0);
    sts(0);
    __syncthreads();

    for (int sub = 0; sub < 8; sub++) {
        const int cur = sub & 1;
        if (sub < 7) ldg(sub + 1);
        const float* Ah = sm + cur * 2560;
        const float* Al = sm + 5120 + cur * 2560;
        const float* Bh = sm + 10240 + cur * 2560;
        const float* Bl = sm + 15360 + cur * 2560;
#pragma unroll
        for (int ks = 0; ks < 2; ks++) {
            const int k0 = ks * 8;
            const float* Ab  = &Ah[(wco + g4) * 20 + k0 + l4];
            const float* Alb = &Al[(wco + g4) * 20 + k0 + l4];
            uint32_t ah0 = __float_as_uint(Ab[0]);
            uint32_t ah1 = __float_as_uint(Ab[8 * 20]);
            uint32_t ah2 = __float_as_uint(Ab[4]);
            uint32_t ah3 = __float_as_uint(Ab[8 * 20 + 4]);
            uint32_t al0 = __float_as_uint(Alb[0]);
            uint32_t al1 = __float_as_uint(Alb[8 * 20]);
            uint32_t al2 = __float_as_uint(Alb[4]);
            uint32_t al3 = __float_as_uint(Alb[8 * 20 + 4]);
#pragma unroll
            for (int tile = 0; tile < 16; tile++) {
                const float* Bb  = &Bh[(tile * 8 + g4) * 20 + k0 + l4];
                const float* Blb = &Bl[(tile * 8 + g4) * 20 + k0 + l4];
                uint32_t bh0 = __float_as_uint(Bb[0]);
                uint32_t bh1 = __float_as_uint(Bb[4]);
                uint32_t bl0 = __float_as_uint(Blb[0]);
                uint32_t bl1 = __float_as_uint(Blb[4]);
                mma_tf32(c[tile], ah0, ah1, ah2, ah3, bh0, bh1);
                mma_tf32(c[tile], ah0, ah1, ah2, ah3, bl0, bl1);
                mma_tf32(c[tile], al0, al1, al2, al3, bh0, bh1);
            }
        }
        if (sub < 7) {
            sts(cur ^ 1);
            __syncthreads();
        }
    }

    float* up = g_up + ((size_t)(n * 32 + kc)) * C_ * C_;
    const int r0 = wco + g4, r1 = wco + g4 + 8;
#pragma unroll
    for (int tile = 0; tile < 16; tile++) {
        const int cix = tile * 8 + l4 * 2;
        *reinterpret_cast<float2*>(&up[(size_t)r0 * 128 + cix]) =
            make_float2(c[tile][0], c[tile][1]);
        *reinterpret_cast<float2*>(&up[(size_t)r1 * 128 + cix]) =
            make_float2(c[tile][2], c[tile][3]);
    }
}

// K3b: reduce 32 split-K partials; write u transposed: g_u[n][ci][co]
__global__ void k3_red()
{
    int o = blockIdx.x * 256 + threadIdx.x;   // 131072
    int n = o >> 14, r = o & 16383;
    float s = 0.f;
#pragma unroll
    for (int kc = 0; kc < 32; kc++)
        s += g_up[(((size_t)(n * 32 + kc)) << 14) + r];
    int co = r >> 7, ci = r & 127;
    g_u[((size_t)n << 14) + ci * 128 + co] = s;
}

// ---------------------------------------------------------------------------
// K4: out = max( s3 * sum_ci u[n,co,ci]*t2[ci,p],  x[co,p] - 0.2*sum_jj t7 taps )
// ---------------------------------------------------------------------------
__global__ void k4_out(const float* __restrict__ x, const float* __restrict__ p1,
                       float* __restrict__ out)
{
    __shared__ __align__(16) float xs [128 * 64];     // t2[ci][w], later t7[co][w]
    __shared__ __align__(16) float as2[2][2048];      // u chunks [kk=ci][co]
    const int row = blockIdx.x, n = blockIdx.y;
    const int t = threadIdx.x;  // 128
    const int tx = t & 7, ty = t >> 3;
    const float* xn = x + (size_t)n * C_ * HW + row * 64;
    const float* un = g_u + ((size_t)n << 14);

#pragma unroll
    for (int r = 0; r < 4; r++)
        cpa16(s2u(&as2[0][r * 512 + t * 4]), &un[r * 512 + t * 4]);
    cpa_commit();

#pragma unroll
    for (int r = 0; r < 16; r++) {
        int idx4 = r * 512 + t * 4;
        int ci = idx4 >> 6, w = idx4 & 63;
        float s = 1.f + p1[ci * 64 + row];
        float4 v = *reinterpret_cast<const float4*>(&xn[(size_t)ci * HW + w]);
        v.x *= s; v.y *= s; v.z *= s; v.w *= s;
        *reinterpret_cast<float4*>(&xs[idx4]) = v;
    }

    u64 acc[4][8];
#pragma unroll
    for (int p = 0; p < 4; p++)
#pragma unroll
        for (int j = 0; j < 8; j++) acc[p][j] = 0ull;

    cpa_wait0();
    __syncthreads();

    for (int kb = 0; kb < 8; kb++) {
        const int cur = kb & 1;
        if (kb < 7) {
#pragma unroll
            for (int r = 0; r < 4; r++)
                cpa16(s2u(&as2[cur ^ 1][r * 512 + t * 4]),
                      &un[(kb + 1) * 2048 + r * 512 + t * 4]);
            cpa_commit();
        }
#pragma unroll
        for (int kk = 0; kk < 16; kk++) {
            int k = kb * 16 + kk;
            float4 b0 = *reinterpret_cast<const float4*>(&xs[k * 64 + tx * 8]);
            float4 b1 = *reinterpret_cast<const float4*>(&xs[k * 64 + tx * 8 + 4]);
            u64 a0 = *reinterpret_cast<const u64*>(&as2[cur][kk * 128 + ty * 8 + 0]);
            u64 a1 = *reinterpret_cast<const u64*>(&as2[cur][kk * 128 + ty * 8 + 2]);
            u64 a2 = *reinterpret_cast<const u64*>(&as2[cur][kk * 128 + ty * 8 + 4]);
            u64 a3 = *reinterpret_cast<const u64*>(&as2[cur][kk * 128 + ty * 8 + 6]);
            u64 bb[8];
            bb[0] = pack2(b0.x, b0.x); bb[1] = pack2(b0.y, b0.y);
            bb[2] = pack2(b0.z, b0.z); bb[3] = pack2(b0.w, b0.w);
            bb[4] = pack2(b1.x, b1.x); bb[5] = pack2(b1.y, b1.y);
            bb[6] = pack2(b1.z, b1.z); bb[7] = pack2(b1.w, b1.w);
#pragma unroll
            for (int j = 0; j < 8; j++) {
                fma2(acc[0][j], a0, bb[j]);
                fma2(acc[1][j], a1, bb[j]);
                fma2(acc[2][j], a2, bb[j]);
                fma2(acc[3][j], a3, bb[j]);
            }
        }
        if (kb < 7) { cpa_wait0(); __syncthreads(); }
    }

    // epilogue: reuse xs for t7[n,:,row,:]
    __syncthreads();
#pragma unroll
    for (int r = 0; r < 16; r++) {
        int idx4 = r * 512 + t * 4;
        int ci = idx4 >> 6, w = idx4 & 63;
        *reinterpret_cast<float4*>(&xs[idx4]) =
            *reinterpret_cast<const float4*>(
                &g_t7[((size_t)n * C_ + ci) * HW + row * 64 + w]);
    }
    __syncthreads();

    const float s3 = 0.01928793f;    // 1/sqrt(2688)
#pragma unroll
    for (int p = 0; p < 4; p++) {
#pragma unroll
        for (int half = 0; half < 2; half++) {
            int co = ty * 8 + 2 * p + half;
            const float* xr = xn + (size_t)co * HW;
            float4 xv0 = *reinterpret_cast<const float4*>(&xr[tx * 8]);
            float4 xv1 = *reinterpret_cast<const float4*>(&xr[tx * 8 + 4]);
            float xv[8] = {xv0.x, xv0.y, xv0.z, xv0.w, xv1.x, xv1.y, xv1.z, xv1.w};
            float res[8];
#pragma unroll
            for (int j = 0; j < 8; j++) {
                int pp = tx * 8 + j;
                float a = half ? hi2(acc[p][j]) : lo2(acc[p][j]);
                float sum = 0.f;
#pragma unroll
                for (int jj = 0; jj < 5; jj++) {
                    int wp = pp + 3 * jj - 6;
                    if ((unsigned)wp < 64u) sum += xs[co * 64 + wp];
                }
                float t12 = xv[j] - 0.2f * sum;
                res[j] = fmaxf(s3 * a, t12);
            }
            float* orow = out + ((size_t)n * C_ + co) * HW + row * 64;
            *reinterpret_cast<float4*>(&orow[tx * 8]) =
                make_float4(res[0], res[1], res[2], res[3]);
            *reinterpret_cast<float4*>(&orow[tx * 8 + 4]) =
                make_float4(res[4], res[5], res[6], res[7]);
        }
    }
}

// ---------------------------------------------------------------------------
extern "C" void kernel_launch(void* const* d_in, const int* in_sizes, int n_in,
                              void* d_out, int out_size)
{
    const float* x   = (const float*)d_in[0];   // (8,128,64,64)
    const float* p1w = (const float*)d_in[1];   // (1,128,64,1)
    const float* p7w = (const float*)d_in[2];   // (128,128)
    const float* p10 = (const float*)d_in[3];   // (2688,32)
    float* out = (float*)d_out;

    const int k1_smem = 18944 * 4;   // 75776 B
    const int k3_smem = 20480 * 4;   // 81920 B
    cudaFuncSetAttribute(k1_mma, cudaFuncAttributeMaxDynamicSharedMemorySize, k1_smem);
    cudaFuncSetAttribute(k3_mma, cudaFuncAttributeMaxDynamicSharedMemorySize, k3_smem);

    k0_prep<<<64, 256>>>(p7w);
    k1_mma <<<dim3(32, 8), 256, k1_smem>>>(x);
    k2_conv<<<dim3(16, 4, 8), 128>>>(x, p10);
    k3_mma <<<dim3(32, 8), 256, k3_smem>>>(x, p1w);
    k3_red <<<512, 256>>>();
    k4_out <<<dim3(64, 8), 128>>>(x, p1w, out);
}

// round 16
// speedup vs baseline: 1.1225x; 1.0752x over previous
#include <cuda_runtime.h>
#include <cstdint>

#define N_ 8
#define C_ 128
#define H_ 64
#define W_ 64
#define HW 4096

typedef unsigned long long u64;

// scratch (no allocs allowed)
__device__ float g_t7 [N_ * C_ * HW];            // 16 MB
__device__ float g_y  [N_ * C_ * HW];            // 16 MB
__device__ float g_up [N_ * 32 * C_ * C_];       // 16 MB split-K partials
__device__ float g_u  [N_ * C_ * C_];            // 512 KB (transposed: [n][ci][co])
__device__ float g_p7h[C_ * C_];                 // p7 tf32-hi  [co][ci]
__device__ float g_p7l[C_ * C_];                 // p7 residual [co][ci]
__device__ float g_wh [4 * 32 * 32 * 28];        // conv W tf32-hi [g][ci][cin][28tap]
__device__ float g_wl [4 * 32 * 32 * 28];        // conv W residual

// ---- helpers ---------------------------------------------------------------
__device__ __forceinline__ u64 pack2(float a, float b) {
    u64 r;
    asm("mov.b64 %0, {%1, %2};" : "=l"(r) : "f"(a), "f"(b));
    return r;
}
__device__ __forceinline__ void fma2(u64& d, u64 a, u64 b) {
    asm("fma.rn.f32x2 %0, %1, %2, %0;" : "+l"(d) : "l"(a), "l"(b));
}
__device__ __forceinline__ float lo2(u64 v) { return __uint_as_float((unsigned)v); }
__device__ __forceinline__ float hi2(u64 v) { return __uint_as_float((unsigned)(v >> 32)); }

__device__ __forceinline__ uint32_t s2u(const void* p) {
    return (uint32_t)__cvta_generic_to_shared(p);
}
__device__ __forceinline__ void cpa16(uint32_t dst, const void* src) {
    asm volatile("cp.async.cg.shared.global [%0], [%1], 16;" :: "r"(dst), "l"(src));
}
__device__ __forceinline__ void cpa_commit() {
    asm volatile("cp.async.commit_group;" ::: "memory");
}
__device__ __forceinline__ void cpa_wait0() {
    asm volatile("cp.async.wait_group 0;" ::: "memory");
}
// cvt.rna.tf32.f32 needs a .b32 destination (ptxas rejects .f32 dst).
__device__ __forceinline__ uint32_t tf32_bits(float v) {
    uint32_t h;
    asm("cvt.rna.tf32.f32 %0, %1;" : "=r"(h) : "f"(v));
    return h;
}
__device__ __forceinline__ void tf32_split(float v, float& hf, float& lf) {
    uint32_t hb = tf32_bits(v);
    hf = __uint_as_float(hb);
    float lo = v - hf;
    lf = __uint_as_float(tf32_bits(lo));
}
// D += A(16x8,row) * B(8x8,col)  tf32
__device__ __forceinline__ void mma_tf32(float* c, uint32_t a0, uint32_t a1,
                                         uint32_t a2, uint32_t a3,
                                         uint32_t b0, uint32_t b1) {
    asm volatile(
        "mma.sync.aligned.m16n8k8.row.col.f32.tf32.tf32.f32 "
        "{%0,%1,%2,%3}, {%4,%5,%6,%7}, {%8,%9}, {%0,%1,%2,%3};"
        : "+f"(c[0]), "+f"(c[1]), "+f"(c[2]), "+f"(c[3])
        : "r"(a0), "r"(a1), "r"(a2), "r"(a3), "r"(b0), "r"(b1));
}

// ---------------------------------------------------------------------------
// K0a: pre-split p7 into tf32 hi/lo ([co][ci] row-major)
// ---------------------------------------------------------------------------
__global__ void k0_prep(const float* __restrict__ p7)
{
    int idx = blockIdx.x * 256 + threadIdx.x;   // 16384
    float h, l;
    tf32_split(p7[idx], h, l);
    g_p7h[idx] = h;
    g_p7l[idx] = l;
}

// ---------------------------------------------------------------------------
// K0b: pre-split conv weights into tf32 hi/lo, taps padded 21->28 (pad = 0).
// layout: g_wh[((g*32+ci)*32 + cin)*28 + tap] = W(g,ci,tap,cin)
// original: p10[((g*32+ci)*21 + tap)*32 + cin]
// ---------------------------------------------------------------------------
__global__ void k0_wprep(const float* __restrict__ p10)
{
    int idx = blockIdx.x * 256 + threadIdx.x;   // 114688
    if (idx >= 4 * 32 * 32 * 28) return;
    int tap = idx % 28;
    int cin = (idx / 28) % 32;
    int cig = idx / 896;                        // g*32 + ci
    float v = (tap < 21) ? p10[((size_t)cig * 21 + tap) * 32 + cin] : 0.f;
    float h, l;
    tf32_split(v, h, l);
    g_wh[idx] = h;
    g_wl[idx] = l;
}

// ---------------------------------------------------------------------------
// K1 (mma.sync tf32, pipelined): t7 = p7 @ relu(x)   [unchanged from R15]
// ---------------------------------------------------------------------------
__global__ void __launch_bounds__(256) k1_mma(const float* __restrict__ x)
{
    extern __shared__ __align__(16) float sm[];
    const int t = threadIdx.x;
    const int pt = blockIdx.x, n = blockIdx.y;
    const int p0 = pt * 128;
    const int wid = t >> 5, lane = t & 31;
    const int g4 = lane >> 2, l4 = lane & 3;
    const int wco = wid * 16;
    const float* xn = x + (size_t)n * C_ * HW;

    float c[16][4];
#pragma unroll
    for (int i = 0; i < 16; i++)
#pragma unroll
        for (int j = 0; j < 4; j++) c[i][j] = 0.f;

    float4 bx[2];
    auto ldgB = [&](int sub) {
        const int ci0 = sub * 16;
#pragma unroll
        for (int k = 0; k < 2; k++) {
            int fi = t + k * 256;
            int ci = fi >> 5, pq = (fi & 31) * 4;
            bx[k] = *reinterpret_cast<const float4*>(
                &xn[(size_t)(ci0 + ci) * HW + p0 + pq]);
        }
    };
    auto cpaA = [&](int sub, int b) {
        const int ci0 = sub * 16;
        float* Ah = sm + b * 2560;
        float* Al = sm + 5120 + b * 2560;
#pragma unroll
        for (int k = 0; k < 2; k++) {
            int fi = t + k * 256;
            int co = fi >> 2, q = (fi & 3) * 4;
            cpa16(s2u(&Ah[co * 20 + q]), &g_p7h[co * 128 + ci0 + q]);
            cpa16(s2u(&Al[co * 20 + q]), &g_p7l[co * 128 + ci0 + q]);
        }
        cpa_commit();
    };
    auto stsB = [&](int b) {
        float* Bh = sm + 10240 + b * 2176;
        float* Bl = sm + 14592 + b * 2176;
#pragma unroll
        for (int k = 0; k < 2; k++) {
            int fi = t + k * 256;
            int ci = fi >> 5, pq = (fi & 31) * 4;
            float4 vh, vl;
            tf32_split(fmaxf(bx[k].x, 0.f), vh.x, vl.x);
            tf32_split(fmaxf(bx[k].y, 0.f), vh.y, vl.y);
            tf32_split(fmaxf(bx[k].z, 0.f), vh.z, vl.z);
            tf32_split(fmaxf(bx[k].w, 0.f), vh.w, vl.w);
            *reinterpret_cast<float4*>(&Bh[ci * 136 + pq]) = vh;
            *reinterpret_cast<float4*>(&Bl[ci * 136 + pq]) = vl;
        }
    };

    ldgB(0);
    cpaA(0, 0);
    stsB(0);
    cpa_wait0();
    __syncthreads();

    for (int sub = 0; sub < 8; sub++) {
        const int cur = sub & 1;
        if (sub < 7) {
            ldgB(sub + 1);
            cpaA(sub + 1, cur ^ 1);
        }
        const float* Ah = sm + cur * 2560;
        const float* Al = sm + 5120 + cur * 2560;
        const float* Bh = sm + 10240 + cur * 2176;
        const float* Bl = sm + 14592 + cur * 2176;
#pragma unroll
        for (int ks = 0; ks < 2; ks++) {
            const int k0 = ks * 8;
            const float* Ab  = &Ah[(wco + g4) * 20 + k0 + l4];
            const float* Alb = &Al[(wco + g4) * 20 + k0 + l4];
            uint32_t ah0 = __float_as_uint(Ab[0]);
            uint32_t ah1 = __float_as_uint(Ab[8 * 20]);
            uint32_t ah2 = __float_as_uint(Ab[4]);
            uint32_t ah3 = __float_as_uint(Ab[8 * 20 + 4]);
            uint32_t al0 = __float_as_uint(Alb[0]);
            uint32_t al1 = __float_as_uint(Alb[8 * 20]);
            uint32_t al2 = __float_as_uint(Alb[4]);
            uint32_t al3 = __float_as_uint(Alb[8 * 20 + 4]);
#pragma unroll
            for (int tile = 0; tile < 16; tile++) {
                const float* Bb  = &Bh[(k0 + l4) * 136 + tile * 8 + g4];
                const float* Blb = &Bl[(k0 + l4) * 136 + tile * 8 + g4];
                uint32_t bh0 = __float_as_uint(Bb[0]);
                uint32_t bh1 = __float_as_uint(Bb[4 * 136]);
                uint32_t bl0 = __float_as_uint(Blb[0]);
                uint32_t bl1 = __float_as_uint(Blb[4 * 136]);
                mma_tf32(c[tile], ah0, ah1, ah2, ah3, bh0, bh1);
                mma_tf32(c[tile], ah0, ah1, ah2, ah3, bl0, bl1);
                mma_tf32(c[tile], al0, al1, al2, al3, bh0, bh1);
            }
        }
        if (sub < 7) {
            stsB(cur ^ 1);
            cpa_wait0();
            __syncthreads();
        }
    }

    float* t7n = g_t7 + (size_t)n * C_ * HW;
    const int r0 = wco + g4, r1 = wco + g4 + 8;
#pragma unroll
    for (int tile = 0; tile < 16; tile++) {
        const int p = p0 + tile * 8 + l4 * 2;
        *reinterpret_cast<float2*>(&t7n[(size_t)r0 * HW + p]) =
            make_float2(c[tile][0], c[tile][1]);
        *reinterpret_cast<float2*>(&t7n[(size_t)r1 * HW + p]) =
            make_float2(c[tile][2], c[tile][3]);
    }
}

// ---------------------------------------------------------------------------
// K2 (mma.sync tf32 implicit GEMM): grouped 3x7 conv
// y[n, g*32+cin, h, w] = sum_{ci,tap} W(g,ci,tap,cin) * x[n, g*32+ci, h+di-1, w+dj-3]
// Block (hs, g, n): M=32 cin (2 m-tiles), N=512 (warp=h row, 8 n-tiles of 8 w),
// K = 32 ci x 24 padded taps (3 chunks of 8). Double-buffered per-ci W + patch.
// B frags read directly from the x patch via per-lane (di,dj).
// ---------------------------------------------------------------------------
__global__ void __launch_bounds__(256, 2) k2_mma(const float* __restrict__ x)
{
    __shared__ __align__(16) float Axh[2][32 * 28];  // W hi  [cin][tap]
    __shared__ __align__(16) float Axl[2][32 * 28];  // W lo
    __shared__ __align__(16) float Pxh[2][11 * 72];  // x patch hi [pr][pc]
    __shared__ __align__(16) float Pxl[2][11 * 72];  // x patch lo

    const int t = threadIdx.x;
    const int hs = blockIdx.x, g = blockIdx.y, n = blockIdx.z;
    const int h0 = hs * 8;
    const int wid = t >> 5, lane = t & 31;      // wid = local h row
    const int g4 = lane >> 2, l4 = lane & 3;

    float c[2][8][4];
#pragma unroll
    for (int mt = 0; mt < 2; mt++)
#pragma unroll
        for (int nt = 0; nt < 8; nt++)
#pragma unroll
            for (int j = 0; j < 4; j++) c[mt][nt][j] = 0.f;

    auto fillW = [&](int ci, int b) {
        const size_t base = ((size_t)(g * 32 + ci) * 32) * 28;
        if (t < 224) {
            int row = t / 7, off = (t % 7) * 4;
            cpa16(s2u(&Axh[b][row * 28 + off]), &g_wh[base + row * 28 + off]);
            cpa16(s2u(&Axl[b][row * 28 + off]), &g_wl[base + row * 28 + off]);
        }
        cpa_commit();
    };

    float pv[4];
    auto ldgP = [&](int ci) {
        const float* xc = x + (size_t)(n * C_ + g * 32 + ci) * HW;
#pragma unroll
        for (int k = 0; k < 4; k++) {
            int i = t + k * 256;
            float v = 0.f;
            if (i < 770) {
                int pr = i / 70, pc = i - pr * 70;
                int hg = h0 - 1 + pr, wg = pc - 3;
                if ((unsigned)hg < 64u && (unsigned)wg < 64u)
                    v = __ldg(&xc[hg * 64 + wg]);
            }
            pv[k] = v;
        }
    };
    auto stsP = [&](int b) {
#pragma unroll
        for (int k = 0; k < 4; k++) {
            int i = t + k * 256;
            if (i < 770) {
                int pr = i / 70, pc = i - pr * 70;
                float h, l;
                tf32_split(pv[k], h, l);
                Pxh[b][pr * 72 + pc] = h;
                Pxl[b][pr * 72 + pc] = l;
            }
        }
    };

    ldgP(0);
    fillW(0, 0);
    stsP(0);
    cpa_wait0();
    __syncthreads();

    for (int ci = 0; ci < 32; ci++) {
        const int cur = ci & 1;
        if (ci < 31) {
            ldgP(ci + 1);
            fillW(ci + 1, cur ^ 1);
        }
        const float* Wh = Axh[cur];
        const float* Wl = Axl[cur];
        const float* Ph = Pxh[cur];
        const float* Pl = Pxl[cur];
#pragma unroll
        for (int c3 = 0; c3 < 3; c3++) {
            const int k0 = c3 * 8;
            uint32_t ah[2][4], al[2][4];
#pragma unroll
            for (int mt = 0; mt < 2; mt++) {
                const float* Ab  = &Wh[(mt * 16 + g4) * 28 + k0 + l4];
                const float* Alb = &Wl[(mt * 16 + g4) * 28 + k0 + l4];
                ah[mt][0] = __float_as_uint(Ab[0]);
                ah[mt][1] = __float_as_uint(Ab[8 * 28]);
                ah[mt][2] = __float_as_uint(Ab[4]);
                ah[mt][3] = __float_as_uint(Ab[8 * 28 + 4]);
                al[mt][0] = __float_as_uint(Alb[0]);
                al[mt][1] = __float_as_uint(Alb[8 * 28]);
                al[mt][2] = __float_as_uint(Alb[4]);
                al[mt][3] = __float_as_uint(Alb[8 * 28 + 4]);
            }
            const int tap0 = k0 + l4, tap1 = tap0 + 4;
            const int di0 = tap0 / 7, dj0 = tap0 - di0 * 7;
            const int di1 = tap1 / 7, dj1 = tap1 - di1 * 7;
            const int base0 = (wid + di0) * 72 + g4 + dj0;
            const int base1 = (wid + di1) * 72 + g4 + dj1;
#pragma unroll
            for (int nt = 0; nt < 8; nt++) {
                uint32_t bh0 = __float_as_uint(Ph[base0 + nt * 8]);
                uint32_t bh1 = __float_as_uint(Ph[base1 + nt * 8]);
                uint32_t bl0 = __float_as_uint(Pl[base0 + nt * 8]);
                uint32_t bl1 = __float_as_uint(Pl[base1 + nt * 8]);
#pragma unroll
                for (int mt = 0; mt < 2; mt++) {
                    mma_tf32(c[mt][nt], ah[mt][0], ah[mt][1], ah[mt][2], ah[mt][3], bh0, bh1);
                    mma_tf32(c[mt][nt], ah[mt][0], ah[mt][1], ah[mt][2], ah[mt][3], bl0, bl1);
                    mma_tf32(c[mt][nt], al[mt][0], al[mt][1], al[mt][2], al[mt][3], bh0, bh1);
                }
            }
        }
        if (ci < 31) {
            stsP(cur ^ 1);
            cpa_wait0();
            __syncthreads();
        }
    }

    // epilogue: y[n][g*32+cin][h0+wid][w]
    const int h = h0 + wid;
#pragma unroll
    for (int mt = 0; mt < 2; mt++) {
        const int cin0 = g * 32 + mt * 16 + g4;
        float* y0 = g_y + ((size_t)(n * C_ + cin0) * 64 + h) * 64;
        float* y1 = g_y + ((size_t)(n * C_ + cin0 + 8) * 64 + h) * 64;
#pragma unroll
        for (int nt = 0; nt < 8; nt++) {
            const int w = nt * 8 + l4 * 2;
            *reinterpret_cast<float2*>(&y0[w]) = make_float2(c[mt][nt][0], c[mt][nt][1]);
            *reinterpret_cast<float2*>(&y1[w]) = make_float2(c[mt][nt][2], c[mt][nt][3]);
        }
    }
}

// ---------------------------------------------------------------------------
// K3 (mma.sync tf32, pipelined): u_part = t1 @ y^T   [unchanged from R15]
// ---------------------------------------------------------------------------
__global__ void __launch_bounds__(256) k3_mma(const float* __restrict__ x,
                                              const float* __restrict__ p1)
{
    extern __shared__ __align__(16) float sm[];
    const int t = threadIdx.x;
    const int kc = blockIdx.x, n = blockIdx.y;
    const int wid = t >> 5, lane = t & 31;
    const int g4 = lane >> 2, l4 = lane & 3;
    const int wco = wid * 16;

    const int p0 = kc * 128;
    const float* xn = x   + (size_t)n * C_ * HW;
    const float* yn = g_y + (size_t)n * C_ * HW;

    float c[16][4];
#pragma unroll
    for (int i = 0; i < 16; i++)
#pragma unroll
        for (int j = 0; j < 4; j++) c[i][j] = 0.f;

    float4 ax[2], ay[2];
    float sA[2];
    auto ldg = [&](int sub) {
        const int pb = p0 + sub * 16;
        const int h = pb >> 6;
#pragma unroll
        for (int k = 0; k < 2; k++) {
            int fi = t + k * 256;
            int row = fi >> 2, q = (fi & 3) * 4;
            sA[k] = p1[row * 64 + h] * (1.f / 64.f);
            ax[k] = *reinterpret_cast<const float4*>(&xn[(size_t)row * HW + pb + q]);
            ay[k] = *reinterpret_cast<const float4*>(&yn[(size_t)row * HW + pb + q]);
        }
    };
    auto sts = [&](int b) {
        float* Ah = sm + b * 2560;
        float* Al = sm + 5120 + b * 2560;
        float* Bh = sm + 10240 + b * 2560;
        float* Bl = sm + 15360 + b * 2560;
#pragma unroll
        for (int k = 0; k < 2; k++) {
            int fi = t + k * 256;
            int row = fi >> 2, q = (fi & 3) * 4;
            float4 vh, vl;
            tf32_split(sA[k] * ax[k].x, vh.x, vl.x);
            tf32_split(sA[k] * ax[k].y, vh.y, vl.y);
            tf32_split(sA[k] * ax[k].z, vh.z, vl.z);
            tf32_split(sA[k] * ax[k].w, vh.w, vl.w);
            *reinterpret_cast<float4*>(&Ah[row * 20 + q]) = vh;
            *reinterpret_cast<float4*>(&Al[row * 20 + q]) = vl;
            tf32_split(ay[k].x, vh.x, vl.x);
            tf32_split(ay[k].y, vh.y, vl.y);
            tf32_split(ay[k].z, vh.z, vl.z);
            tf32_split(ay[k].w, vh.w, vl.w);
            *reinterpret_cast<float4*>(&Bh[row * 20 + q]) = vh;
            *reinterpret_cast<float4*>(&Bl[row * 20 + q]) = vl;
        }
    };

    ldg(0);
    sts(0);
    __syncthreads();

    for (int sub = 0; sub < 8; sub++) {
        const int cur = sub & 1;
        if (sub < 7) ldg(sub + 1);
        const float* Ah = sm + cur * 2560;
        const float* Al = sm + 5120 + cur * 2560;
        const float* Bh = sm + 10240 + cur * 2560;
        const float* Bl = sm + 15360 + cur * 2560;
#pragma unroll
        for (int ks = 0; ks < 2; ks++) {
            const int k0 = ks * 8;
            const float* Ab  = &Ah[(wco + g4) * 20 + k0 + l4];
            const float* Alb = &Al[(wco + g4) * 20 + k0 + l4];
            uint32_t ah0 = __float_as_uint(Ab[0]);
            uint32_t ah1 = __float_as_uint(Ab[8 * 20]);
            uint32_t ah2 = __float_as_uint(Ab[4]);
            uint32_t ah3 = __float_as_uint(Ab[8 * 20 + 4]);
            uint32_t al0 = __float_as_uint(Alb[0]);
            uint32_t al1 = __float_as_uint(Alb[8 * 20]);
            uint32_t al2 = __float_as_uint(Alb[4]);
            uint32_t al3 = __float_as_uint(Alb[8 * 20 + 4]);
#pragma unroll
            for (int tile = 0; tile < 16; tile++) {
                const float* Bb  = &Bh[(tile * 8 + g4) * 20 + k0 + l4];
                const float* Blb = &Bl[(tile * 8 + g4) * 20 + k0 + l4];
                uint32_t bh0 = __float_as_uint(Bb[0]);
                uint32_t bh1 = __float_as_uint(Bb[4]);
                uint32_t bl0 = __float_as_uint(Blb[0]);
                uint32_t bl1 = __float_as_uint(Blb[4]);
                mma_tf32(c[tile], ah0, ah1, ah2, ah3, bh0, bh1);
                mma_tf32(c[tile], ah0, ah1, ah2, ah3, bl0, bl1);
                mma_tf32(c[tile], al0, al1, al2, al3, bh0, bh1);
            }
        }
        if (sub < 7) {
            sts(cur ^ 1);
            __syncthreads();
        }
    }

    float* up = g_up + ((size_t)(n * 32 + kc)) * C_ * C_;
    const int r0 = wco + g4, r1 = wco + g4 + 8;
#pragma unroll
    for (int tile = 0; tile < 16; tile++) {
        const int cix = tile * 8 + l4 * 2;
        *reinterpret_cast<float2*>(&up[(size_t)r0 * 128 + cix]) =
            make_float2(c[tile][0], c[tile][1]);
        *reinterpret_cast<float2*>(&up[(size_t)r1 * 128 + cix]) =
            make_float2(c[tile][2], c[tile][3]);
    }
}

// K3b: reduce 32 split-K partials; write u transposed: g_u[n][ci][co]
__global__ void k3_red()
{
    int o = blockIdx.x * 256 + threadIdx.x;   // 131072
    int n = o >> 14, r = o & 16383;
    float s = 0.f;
#pragma unroll
    for (int kc = 0; kc < 32; kc++)
        s += g_up[(((size_t)(n * 32 + kc)) << 14) + r];
    int co = r >> 7, ci = r & 127;
    g_u[((size_t)n << 14) + ci * 128 + co] = s;
}

// ---------------------------------------------------------------------------
// K4: out = max( s3 * sum_ci u[n,co,ci]*t2[ci,p],  x[co,p] - 0.2*sum_jj t7 taps )
// ---------------------------------------------------------------------------
__global__ void k4_out(const float* __restrict__ x, const float* __restrict__ p1,
                       float* __restrict__ out)
{
    __shared__ __align__(16) float xs [128 * 64];     // t2[ci][w], later t7[co][w]
    __shared__ __align__(16) float as2[2][2048];      // u chunks [kk=ci][co]
    const int row = blockIdx.x, n = blockIdx.y;
    const int t = threadIdx.x;  // 128
    const int tx = t & 7, ty = t >> 3;
    const float* xn = x + (size_t)n * C_ * HW + row * 64;
    const float* un = g_u + ((size_t)n << 14);

#pragma unroll
    for (int r = 0; r < 4; r++)
        cpa16(s2u(&as2[0][r * 512 + t * 4]), &un[r * 512 + t * 4]);
    cpa_commit();

#pragma unroll
    for (int r = 0; r < 16; r++) {
        int idx4 = r * 512 + t * 4;
        int ci = idx4 >> 6, w = idx4 & 63;
        float s = 1.f + p1[ci * 64 + row];
        float4 v = *reinterpret_cast<const float4*>(&xn[(size_t)ci * HW + w]);
        v.x *= s; v.y *= s; v.z *= s; v.w *= s;
        *reinterpret_cast<float4*>(&xs[idx4]) = v;
    }

    u64 acc[4][8];
#pragma unroll
    for (int p = 0; p < 4; p++)
#pragma unroll
        for (int j = 0; j < 8; j++) acc[p][j] = 0ull;

    cpa_wait0();
    __syncthreads();

    for (int kb = 0; kb < 8; kb++) {
        const int cur = kb & 1;
        if (kb < 7) {
#pragma unroll
            for (int r = 0; r < 4; r++)
                cpa16(s2u(&as2[cur ^ 1][r * 512 + t * 4]),
                      &un[(kb + 1) * 2048 + r * 512 + t * 4]);
            cpa_commit();
        }
#pragma unroll
        for (int kk = 0; kk < 16; kk++) {
            int k = kb * 16 + kk;
            float4 b0 = *reinterpret_cast<const float4*>(&xs[k * 64 + tx * 8]);
            float4 b1 = *reinterpret_cast<const float4*>(&xs[k * 64 + tx * 8 + 4]);
            u64 a0 = *reinterpret_cast<const u64*>(&as2[cur][kk * 128 + ty * 8 + 0]);
            u64 a1 = *reinterpret_cast<const u64*>(&as2[cur][kk * 128 + ty * 8 + 2]);
            u64 a2 = *reinterpret_cast<const u64*>(&as2[cur][kk * 128 + ty * 8 + 4]);
            u64 a3 = *reinterpret_cast<const u64*>(&as2[cur][kk * 128 + ty * 8 + 6]);
            u64 bb[8];
            bb[0] = pack2(b0.x, b0.x); bb[1] = pack2(b0.y, b0.y);
            bb[2] = pack2(b0.z, b0.z); bb[3] = pack2(b0.w, b0.w);
            bb[4] = pack2(b1.x, b1.x); bb[5] = pack2(b1.y, b1.y);
            bb[6] = pack2(b1.z, b1.z); bb[7] = pack2(b1.w, b1.w);
#pragma unroll
            for (int j = 0; j < 8; j++) {
                fma2(acc[0][j], a0, bb[j]);
                fma2(acc[1][j], a1, bb[j]);
                fma2(acc[2][j], a2, bb[j]);
                fma2(acc[3][j], a3, bb[j]);
            }
        }
        if (kb < 7) { cpa_wait0(); __syncthreads(); }
    }

    // epilogue: reuse xs for t7[n,:,row,:]
    __syncthreads();
#pragma unroll
    for (int r = 0; r < 16; r++) {
        int idx4 = r * 512 + t * 4;
        int ci = idx4 >> 6, w = idx4 & 63;
        *reinterpret_cast<float4*>(&xs[idx4]) =
            *reinterpret_cast<const float4*>(
                &g_t7[((size_t)n * C_ + ci) * HW + row * 64 + w]);
    }
    __syncthreads();

    const float s3 = 0.01928793f;    // 1/sqrt(2688)
#pragma unroll
    for (int p = 0; p < 4; p++) {
#pragma unroll
        for (int half = 0; half < 2; half++) {
            int co = ty * 8 + 2 * p + half;
            const float* xr = xn + (size_t)co * HW;
            float4 xv0 = *reinterpret_cast<const float4*>(&xr[tx * 8]);
            float4 xv1 = *reinterpret_cast<const float4*>(&xr[tx * 8 + 4]);
            float xv[8] = {xv0.x, xv0.y, xv0.z, xv0.w, xv1.x, xv1.y, xv1.z, xv1.w};
            float res[8];
#pragma unroll
            for (int j = 0; j < 8; j++) {
                int pp = tx * 8 + j;
                float a = half ? hi2(acc[p][j]) : lo2(acc[p][j]);
                float sum = 0.f;
#pragma unroll
                for (int jj = 0; jj < 5; jj++) {
                    int wp = pp + 3 * jj - 6;
                    if ((unsigned)wp < 64u) sum += xs[co * 64 + wp];
                }
                float t12 = xv[j] - 0.2f * sum;
                res[j] = fmaxf(s3 * a, t12);
            }
            float* orow = out + ((size_t)n * C_ + co) * HW + row * 64;
            *reinterpret_cast<float4*>(&orow[tx * 8]) =
                make_float4(res[0], res[1], res[2], res[3]);
            *reinterpret_cast<float4*>(&orow[tx * 8 + 4]) =
                make_float4(res[4], res[5], res[6], res[7]);
        }
    }
}

// ---------------------------------------------------------------------------
extern "C" void kernel_launch(void* const* d_in, const int* in_sizes, int n_in,
                              void* d_out, int out_size)
{
    const float* x   = (const float*)d_in[0];   // (8,128,64,64)
    const float* p1w = (const float*)d_in[1];   // (1,128,64,1)
    const float* p7w = (const float*)d_in[2];   // (128,128)
    const float* p10 = (const float*)d_in[3];   // (2688,32)
    float* out = (float*)d_out;

    const int k1_smem = 18944 * 4;   // 75776 B
    const int k3_smem = 20480 * 4;   // 81920 B
    cudaFuncSetAttribute(k1_mma, cudaFuncAttributeMaxDynamicSharedMemorySize, k1_smem);
    cudaFuncSetAttribute(k3_mma, cudaFuncAttributeMaxDynamicSharedMemorySize, k3_smem);

    k0_prep <<<64, 256>>>(p7w);
    k0_wprep<<<448, 256>>>(p10);
    k1_mma  <<<dim3(32, 8), 256, k1_smem>>>(x);
    k2_mma  <<<dim3(8, 4, 8), 256>>>(x);
    k3_mma  <<<dim3(32, 8), 256, k3_smem>>>(x, p1w);
    k3_red  <<<512, 256>>>();
    k4_out  <<<dim3(64, 8), 128>>>(x, p1w, out);
}